// round 3
// baseline (speedup 1.0000x reference)
#include <cuda_runtime.h>
#include <cuda_bf16.h>
#include <math.h>

// ---------------- problem constants ----------------
#define BATCH   8
#define CCH     256        // D_MODEL
#define LSEQ    4096       // H*W
#define ROWS    (BATCH*LSEQ)        // 32768
#define DIN     1064       // D_IN_PROJ
#define DINNER  512
#define CONVD   544
#define NH      8
#define HD      64
#define DS      16
#define EPS     1e-5f

// chunked scan
#define SEG     64         // segments per sequence
#define SLEN    (LSEQ/SEG) // 64 timesteps per segment
#define NBH     (BATCH*NH) // 64
#define STATE   (HD*DS)    // 1024 floats per (b,h) state

// ---------------- scratch (static device memory; no allocs allowed) ----------
__device__ float g_un [(size_t)ROWS*CCH];
__device__ float g_zx [(size_t)ROWS*DIN];
__device__ float g_xbc[(size_t)ROWS*CONVD];
__device__ float g_dt [(size_t)ROWS*NH];
__device__ float g_da [(size_t)ROWS*NH];
__device__ float g_y  [(size_t)ROWS*DINNER];
__device__ float g_yn [(size_t)ROWS*DINNER];
__device__ float g_o  [(size_t)ROWS*CCH];
__device__ float g_hend[(size_t)NBH*SEG*STATE];
__device__ float g_hin [(size_t)NBH*SEG*STATE];
__device__ float g_P   [(size_t)NBH*SEG];

// ---------------- kernel 1: layernorm with transpose-read ----------------
__global__ __launch_bounds__(256) void ln_kernel(
    const float* __restrict__ x, const float* __restrict__ gamma,
    const float* __restrict__ beta)
{
    __shared__ float s[256][33];
    __shared__ float s_mu[32], s_rs[32];
    const int b  = blockIdx.y;
    const int l0 = blockIdx.x * 32;
    const int t  = threadIdx.x;

#pragma unroll
    for (int i = 0; i < 32; i++) {
        int flat = i * 256 + t;
        int c  = flat >> 5;
        int lp = flat & 31;
        s[c][lp] = x[((size_t)b * CCH + c) * LSEQ + l0 + lp];
    }
    __syncthreads();

    const int wid = t >> 5, lane = t & 31;
    for (int j = wid; j < 32; j += 8) {
        float v = 0.f, v2 = 0.f;
#pragma unroll
        for (int k = 0; k < 8; k++) {
            float a = s[lane + 32 * k][j];
            v += a; v2 += a * a;
        }
#pragma unroll
        for (int o = 16; o; o >>= 1) {
            v  += __shfl_xor_sync(0xffffffffu, v,  o);
            v2 += __shfl_xor_sync(0xffffffffu, v2, o);
        }
        if (lane == 0) {
            float m = v * (1.f / 256.f);
            s_mu[j] = m;
            s_rs[j] = rsqrtf(v2 * (1.f / 256.f) - m * m + EPS);
        }
    }
    __syncthreads();

#pragma unroll
    for (int i = 0; i < 32; i++) {
        int flat = i * 256 + t;
        int lp = flat >> 8;
        int c  = flat & 255;
        float v = (s[c][lp] - s_mu[lp]) * s_rs[lp] * gamma[c] + beta[c];
        g_un[((size_t)b * LSEQ + l0 + lp) * CCH + c] = v;
    }
}

// ---------------- tiled fp32 GEMM: C = A(MxK) * B(KxN) ----------------
template<int BM, int BN, int BK, int TM, int TN>
__global__ __launch_bounds__(256) void gemm_kernel(
    const float* __restrict__ A, const float* __restrict__ B,
    float* __restrict__ C, int M, int N, int K)
{
    __shared__ float As[BK][BM + 4];
    __shared__ float Bs[BK][BN];
    const int t  = threadIdx.x;
    const int tx = t % (BN / TN);
    const int ty = t / (BN / TN);
    const int m0 = blockIdx.y * BM;
    const int n0 = blockIdx.x * BN;

    float acc[TM][TN];
#pragma unroll
    for (int i = 0; i < TM; i++)
#pragma unroll
        for (int j = 0; j < TN; j++) acc[i][j] = 0.f;

    for (int k0 = 0; k0 < K; k0 += BK) {
#pragma unroll
        for (int i = t; i < BM * BK; i += 256) {
            int m = i / BK, k = i % BK;
            As[k][m] = A[(size_t)(m0 + m) * K + k0 + k];
        }
#pragma unroll
        for (int i = t; i < BK * BN; i += 256) {
            int k = i / BN, n = i % BN;
            float v = 0.f;
            if (n0 + n < N) v = B[(size_t)(k0 + k) * N + n0 + n];
            Bs[k][n] = v;
        }
        __syncthreads();

#pragma unroll
        for (int k = 0; k < BK; k++) {
            float a[TM], bb[TN];
#pragma unroll
            for (int i = 0; i < TM; i++) a[i] = As[k][ty * TM + i];
            float4 b4 = *(const float4*)&Bs[k][tx * TN];
            bb[0] = b4.x; bb[1] = b4.y; bb[2] = b4.z; bb[3] = b4.w;
#pragma unroll
            for (int i = 0; i < TM; i++)
#pragma unroll
                for (int j = 0; j < TN; j++)
                    acc[i][j] = fmaf(a[i], bb[j], acc[i][j]);
        }
        __syncthreads();
    }

#pragma unroll
    for (int i = 0; i < TM; i++) {
        int m = m0 + ty * TM + i;
#pragma unroll
        for (int j = 0; j < TN; j++) {
            int n = n0 + tx * TN + j;
            if (n < N) C[(size_t)m * N + n] = acc[i][j];
        }
    }
}

// ---------------- kernel 3: dt = softplus(raw + bias), dA = exp(dt*A) -------
__global__ void dtda_kernel(const float* __restrict__ dt_bias,
                            const float* __restrict__ A_log)
{
    int id = blockIdx.x * blockDim.x + threadIdx.x;
    if (id >= ROWS * NH) return;
    int r = id >> 3, h = id & 7;
    float v = g_zx[(size_t)r * DIN + (DIN - NH) + h] + dt_bias[h];
    float d = (v > 20.f) ? v : log1pf(expf(v));
    float A = -expf(A_log[h]);
    g_dt[id] = d;
    g_da[id] = expf(d * A);
}

// ---------------- kernel 4: causal depthwise conv(4) + SiLU ----------------
__global__ void conv_kernel(const float* __restrict__ cw,
                            const float* __restrict__ cb)
{
    int id = blockIdx.x * blockDim.x + threadIdx.x;
    if (id >= ROWS * CONVD) return;
    int c = id % CONVD;
    int r = id / CONVD;
    int l = r & (LSEQ - 1);

    const float* col = g_zx + DINNER + c;
    float w0 = cw[c * 4 + 0], w1 = cw[c * 4 + 1], w2 = cw[c * 4 + 2], w3 = cw[c * 4 + 3];
    float acc = cb[c] + w3 * col[(size_t)r * DIN];
    if (l >= 1) acc += w2 * col[(size_t)(r - 1) * DIN];
    if (l >= 2) acc += w1 * col[(size_t)(r - 2) * DIN];
    if (l >= 3) acc += w0 * col[(size_t)(r - 3) * DIN];
    float sg = 1.f / (1.f + expf(-acc));
    g_xbc[(size_t)r * CONVD + c] = acc * sg;
}

// ---------------- kernel 5a: segment-local scan ----------------
__global__ __launch_bounds__(64) void scanA_kernel(const float* __restrict__ Dp)
{
    const int blk = blockIdx.x;
    const int bh  = blk / SEG;
    const int seg = blk % SEG;
    const int b = bh >> 3, h = bh & 7;
    const int p = threadIdx.x;
    const float Dh = Dp[h];

    float hs[DS];
#pragma unroll
    for (int n = 0; n < DS; n++) hs[n] = 0.f;
    float prod = 1.f;

    const size_t r0 = (size_t)b * LSEQ + seg * SLEN;
    for (int l = 0; l < SLEN; l++) {
        const size_t r = r0 + l;
        const float* base = g_xbc + r * CONVD;
        float dav = g_da[r * NH + h];
        float dtv = g_dt[r * NH + h];
        float xv  = base[h * HD + p];
        prod *= dav;

        float4 B0 = *(const float4*)(base + DINNER +  0);
        float4 B1 = *(const float4*)(base + DINNER +  4);
        float4 B2 = *(const float4*)(base + DINNER +  8);
        float4 B3 = *(const float4*)(base + DINNER + 12);
        float4 C0 = *(const float4*)(base + DINNER + 16);
        float4 C1 = *(const float4*)(base + DINNER + 20);
        float4 C2 = *(const float4*)(base + DINNER + 24);
        float4 C3 = *(const float4*)(base + DINNER + 28);
        float bb[DS] = {B0.x,B0.y,B0.z,B0.w, B1.x,B1.y,B1.z,B1.w,
                        B2.x,B2.y,B2.z,B2.w, B3.x,B3.y,B3.z,B3.w};
        float cc[DS] = {C0.x,C0.y,C0.z,C0.w, C1.x,C1.y,C1.z,C1.w,
                        C2.x,C2.y,C2.z,C2.w, C3.x,C3.y,C3.z,C3.w};

        float t1 = dtv * xv;
        float yv = 0.f;
#pragma unroll
        for (int n = 0; n < DS; n++) {
            hs[n] = fmaf(dav, hs[n], t1 * bb[n]);
            yv = fmaf(hs[n], cc[n], yv);
        }
        g_y[r * DINNER + h * HD + p] = yv + Dh * xv;
    }

    float* he = g_hend + ((size_t)bh * SEG + seg) * STATE + p * DS;
#pragma unroll
    for (int n = 0; n < DS; n += 4)
        *(float4*)(he + n) = make_float4(hs[n], hs[n+1], hs[n+2], hs[n+3]);
    if (p == 0) g_P[(size_t)bh * SEG + seg] = prod;
}

// ---------------- kernel 5b: compose segment states ----------------
__global__ __launch_bounds__(1024) void scanB_kernel()
{
    const int bh = blockIdx.x;
    const int pn = threadIdx.x;
    __shared__ float sP[SEG];
    if (pn < SEG) sP[pn] = g_P[(size_t)bh * SEG + pn];
    __syncthreads();

    float h = 0.f;
    const size_t base = (size_t)bh * SEG * STATE + pn;
    for (int seg = 0; seg < SEG; seg++) {
        g_hin[base + (size_t)seg * STATE] = h;
        h = fmaf(sP[seg], h, g_hend[base + (size_t)seg * STATE]);
    }
}

// ---------------- kernel 5c: cross-segment correction ----------------
__global__ __launch_bounds__(64) void scanC_kernel()
{
    const int blk = blockIdx.x;
    const int bh  = blk / (SEG - 1);
    const int seg = blk % (SEG - 1) + 1;
    const int b = bh >> 3, h = bh & 7;
    const int p = threadIdx.x;

    float hi[DS];
    const float* hp = g_hin + ((size_t)bh * SEG + seg) * STATE + p * DS;
#pragma unroll
    for (int n = 0; n < DS; n += 4) {
        float4 v = *(const float4*)(hp + n);
        hi[n] = v.x; hi[n+1] = v.y; hi[n+2] = v.z; hi[n+3] = v.w;
    }

    float cp = 1.f;
    const size_t r0 = (size_t)b * LSEQ + seg * SLEN;
    for (int l = 0; l < SLEN; l++) {
        const size_t r = r0 + l;
        const float* base = g_xbc + r * CONVD;
        cp *= g_da[r * NH + h];

        float4 C0 = *(const float4*)(base + DINNER + 16);
        float4 C1 = *(const float4*)(base + DINNER + 20);
        float4 C2 = *(const float4*)(base + DINNER + 24);
        float4 C3 = *(const float4*)(base + DINNER + 28);
        float cc[DS] = {C0.x,C0.y,C0.z,C0.w, C1.x,C1.y,C1.z,C1.w,
                        C2.x,C2.y,C2.z,C2.w, C3.x,C3.y,C3.z,C3.w};

        float dot = 0.f;
#pragma unroll
        for (int n = 0; n < DS; n++) dot = fmaf(hi[n], cc[n], dot);
        g_y[r * DINNER + h * HD + p] += cp * dot;
    }
}

// ---------------- kernel 6: gate with silu(z) + RMSNorm ----------------
__global__ __launch_bounds__(256) void gatenorm_kernel(const float* __restrict__ rms_w)
{
    const int r = blockIdx.x;
    const int t = threadIdx.x;
    __shared__ float red[8];

    float vals[2];
    float sum = 0.f;
#pragma unroll
    for (int j = 0; j < 2; j++) {
        int i = t + j * 256;
        float yv = g_y[(size_t)r * DINNER + i];
        float zv = g_zx[(size_t)r * DIN + i];
        float g = zv / (1.f + expf(-zv));
        float v = yv * g;
        vals[j] = v;
        sum += v * v;
    }
#pragma unroll
    for (int o = 16; o; o >>= 1) sum += __shfl_xor_sync(0xffffffffu, sum, o);
    if ((t & 31) == 0) red[t >> 5] = sum;
    __syncthreads();
    if (t < 8) {
        float v = red[t];
#pragma unroll
        for (int o = 4; o; o >>= 1) v += __shfl_xor_sync(0xffu, v, o);
        if (t == 0) red[0] = v;
    }
    __syncthreads();
    float rn = rsqrtf(red[0] * (1.f / (float)DINNER) + EPS);
#pragma unroll
    for (int j = 0; j < 2; j++) {
        int i = t + j * 256;
        g_yn[(size_t)r * DINNER + i] = vals[j] * rn * rms_w[i];
    }
}

// ---------------- kernel 7: transpose (l,c)->(c,l) + residual add ----------
__global__ void trans_add_kernel(const float* __restrict__ x,
                                 float* __restrict__ out)
{
    __shared__ float tile[32][33];
    const int b  = blockIdx.z;
    const int l0 = blockIdx.y * 32;
    const int c0 = blockIdx.x * 32;
    const int tx = threadIdx.x, ty = threadIdx.y;

#pragma unroll
    for (int i = ty; i < 32; i += 8)
        tile[i][tx] = g_o[((size_t)b * LSEQ + l0 + i) * CCH + c0 + tx];
    __syncthreads();
#pragma unroll
    for (int i = ty; i < 32; i += 8) {
        size_t o = ((size_t)b * CCH + c0 + i) * LSEQ + l0 + tx;
        out[o] = tile[tx][i] + x[o];
    }
}

// helper kernels need raw pointers to globals for the GEMM template;
// take them via device-side symbol decay inside tiny wrapper launches.
__global__ void noop_kernel() {}

extern "C" void kernel_launch(void* const* d_in, const int* in_sizes, int n_in,
                              void* d_out, int out_size)
{
    const float* x       = (const float*)d_in[0];
    const float* ln_g    = (const float*)d_in[1];
    const float* ln_b    = (const float*)d_in[2];
    const float* Win     = (const float*)d_in[3];
    const float* Wout    = (const float*)d_in[4];
    const float* conv_w  = (const float*)d_in[5];
    const float* conv_b  = (const float*)d_in[6];
    const float* dt_bias = (const float*)d_in[7];
    const float* A_log   = (const float*)d_in[8];
    const float* Dp      = (const float*)d_in[9];
    const float* rms_w   = (const float*)d_in[10];
    float* out = (float*)d_out;

    // resolve device-global addresses once (host-side API, not stream work;
    // results are stable addresses — safe both in and out of capture)
    static float *p_un = nullptr, *p_zx, *p_yn, *p_o;
    if (!p_un) {
        cudaGetSymbolAddress((void**)&p_un, g_un);
        cudaGetSymbolAddress((void**)&p_zx, g_zx);
        cudaGetSymbolAddress((void**)&p_yn, g_yn);
        cudaGetSymbolAddress((void**)&p_o,  g_o);
    }

    // 1) layernorm
    ln_kernel<<<dim3(LSEQ / 32, BATCH), 256>>>(x, ln_g, ln_b);

    // 2) in_proj GEMM: (32768x256)@(256x1064)
    gemm_kernel<128, 64, 16, 8, 4><<<dim3((DIN + 63) / 64, ROWS / 128), 256>>>(
        p_un, Win, p_zx, ROWS, DIN, CCH);

    // 3) dt / dA
    dtda_kernel<<<(ROWS * NH + 255) / 256, 256>>>(dt_bias, A_log);

    // 4) conv + silu
    conv_kernel<<<((size_t)ROWS * CONVD + 255) / 256, 256>>>(conv_w, conv_b);

    // 5) segmented SSM scan
    scanA_kernel<<<NBH * SEG, HD>>>(Dp);
    scanB_kernel<<<NBH, STATE>>>();
    scanC_kernel<<<NBH * (SEG - 1), HD>>>();

    // 6) gate + rmsnorm
    gatenorm_kernel<<<ROWS, 256>>>(rms_w);

    // 7) out_proj GEMM: (32768x512)@(512x256)
    gemm_kernel<128, 64, 16, 8, 4><<<dim3(CCH / 64, ROWS / 128), 256>>>(
        p_yn, Wout, p_o, ROWS, CCH, DINNER);

    // 8) transpose + residual
    trans_add_kernel<<<dim3(CCH / 32, LSEQ / 32, BATCH), dim3(32, 8)>>>(x, out);
}

// round 4
// speedup vs baseline: 1.7377x; 1.7377x over previous
#include <cuda_runtime.h>
#include <cuda_bf16.h>
#include <math.h>
#include <stdint.h>

// ---------------- problem constants ----------------
#define BATCH   8
#define CCH     256        // D_MODEL
#define LSEQ    4096       // H*W
#define ROWS    (BATCH*LSEQ)        // 32768
#define DIN     1064       // D_IN_PROJ
#define DINNER  512
#define CONVD   544
#define NH      8
#define HD      64
#define DS      16
#define EPS     1e-5f

// chunked scan
#define SEG     64
#define SLEN    (LSEQ/SEG) // 64
#define NBH     (BATCH*NH) // 64
#define STATE   (HD*DS)    // 1024

// ---------------- scratch ----------------
__device__ float g_un [(size_t)ROWS*CCH];
__device__ float g_zx [(size_t)ROWS*DIN];
__device__ float g_xbc[(size_t)ROWS*CONVD];
__device__ float g_dt [(size_t)ROWS*NH];
__device__ float g_da [(size_t)ROWS*NH];
__device__ float g_y  [(size_t)ROWS*DINNER];
__device__ float g_yn [(size_t)ROWS*DINNER];
__device__ float g_o  [(size_t)ROWS*CCH];
__device__ float g_hend[(size_t)NBH*SEG*STATE];
__device__ float g_hin [(size_t)NBH*SEG*STATE];
__device__ float g_P   [(size_t)NBH*SEG];

// ---------------- kernel 1: layernorm with transpose-read ----------------
__global__ __launch_bounds__(256) void ln_kernel(
    const float* __restrict__ x, const float* __restrict__ gamma,
    const float* __restrict__ beta)
{
    __shared__ float s[256][33];
    __shared__ float s_mu[32], s_rs[32];
    const int b  = blockIdx.y;
    const int l0 = blockIdx.x * 32;
    const int t  = threadIdx.x;

#pragma unroll
    for (int i = 0; i < 32; i++) {
        int flat = i * 256 + t;
        int c  = flat >> 5;
        int lp = flat & 31;
        s[c][lp] = x[((size_t)b * CCH + c) * LSEQ + l0 + lp];
    }
    __syncthreads();

    const int wid = t >> 5, lane = t & 31;
    for (int j = wid; j < 32; j += 8) {
        float v = 0.f, v2 = 0.f;
#pragma unroll
        for (int k = 0; k < 8; k++) {
            float a = s[lane + 32 * k][j];
            v += a; v2 += a * a;
        }
#pragma unroll
        for (int o = 16; o; o >>= 1) {
            v  += __shfl_xor_sync(0xffffffffu, v,  o);
            v2 += __shfl_xor_sync(0xffffffffu, v2, o);
        }
        if (lane == 0) {
            float m = v * (1.f / 256.f);
            s_mu[j] = m;
            s_rs[j] = rsqrtf(v2 * (1.f / 256.f) - m * m + EPS);
        }
    }
    __syncthreads();

#pragma unroll
    for (int i = 0; i < 32; i++) {
        int flat = i * 256 + t;
        int lp = flat >> 8;
        int c  = flat & 255;
        float v = (s[c][lp] - s_mu[lp]) * s_rs[lp] * gamma[c] + beta[c];
        g_un[((size_t)b * LSEQ + l0 + lp) * CCH + c] = v;
    }
}

// ---------------- TF32 tensor-core GEMM: C = A(MxK) * B(KxN) ----------------
// 128x64x32 block tile, 8 warps (4x2), each warp 32x32 via 2x4 m16n8k8 mma.
__device__ __forceinline__ uint32_t f2tf32(float f) {
    uint32_t r;
    asm("cvt.rna.tf32.f32 %0, %1;" : "=r"(r) : "f"(f));
    return r;
}

__global__ __launch_bounds__(256) void gemm_tf32_kernel(
    const float* __restrict__ A, const float* __restrict__ B,
    float* __restrict__ C, int M, int N, int K)
{
    constexpr int BM = 128, BN = 64, BK = 32;
    __shared__ uint32_t As[BM][BK + 4];   // stride 36: frag reads bank = 4g+tg (conflict-free)
    __shared__ uint32_t Bs[BK][BN + 8];   // stride 72: frag reads bank = 8tg+g (conflict-free)

    const int t = threadIdx.x;
    const int warp = t >> 5, lane = t & 31;
    const int wm = warp & 3;          // 0..3
    const int wn = warp >> 2;         // 0..1
    const int m0 = blockIdx.y * BM;
    const int n0 = blockIdx.x * BN;
    const int g = lane >> 2, tg = lane & 3;

    float acc[2][4][4];
#pragma unroll
    for (int mi = 0; mi < 2; mi++)
#pragma unroll
        for (int nj = 0; nj < 4; nj++)
#pragma unroll
            for (int q = 0; q < 4; q++) acc[mi][nj][q] = 0.f;

    for (int k0 = 0; k0 < K; k0 += BK) {
        // A tile: 4 float4 per thread, coalesced along k
#pragma unroll
        for (int i = 0; i < 4; i++) {
            int idx = t + i * 256;          // 0..1023
            int row = idx >> 3;
            int kc  = (idx & 7) << 2;
            float4 v = *(const float4*)(A + (size_t)(m0 + row) * K + k0 + kc);
            As[row][kc + 0] = f2tf32(v.x);
            As[row][kc + 1] = f2tf32(v.y);
            As[row][kc + 2] = f2tf32(v.z);
            As[row][kc + 3] = f2tf32(v.w);
        }
        // B tile: 4 float2 per thread, coalesced along n, guarded on N
#pragma unroll
        for (int i = 0; i < 4; i++) {
            int idx = t + i * 256;          // 0..1023
            int kr = idx >> 5;
            int nc = (idx & 31) << 1;
            float vx = 0.f, vy = 0.f;
            if (n0 + nc < N) {
                const float* bp = B + (size_t)(k0 + kr) * N + n0 + nc;
                vx = bp[0];
                vy = bp[1];                 // N is even, nc even: safe when nc<N
            }
            Bs[kr][nc + 0] = f2tf32(vx);
            Bs[kr][nc + 1] = f2tf32(vy);
        }
        __syncthreads();

#pragma unroll
        for (int kk = 0; kk < BK; kk += 8) {
            uint32_t af[2][4];
#pragma unroll
            for (int mi = 0; mi < 2; mi++) {
                int mb = wm * 32 + mi * 16;
                af[mi][0] = As[mb + g    ][kk + tg];
                af[mi][1] = As[mb + 8 + g][kk + tg];
                af[mi][2] = As[mb + g    ][kk + 4 + tg];
                af[mi][3] = As[mb + 8 + g][kk + 4 + tg];
            }
            uint32_t bf[4][2];
#pragma unroll
            for (int nj = 0; nj < 4; nj++) {
                int nb = wn * 32 + nj * 8;
                bf[nj][0] = Bs[kk + tg    ][nb + g];
                bf[nj][1] = Bs[kk + 4 + tg][nb + g];
            }
#pragma unroll
            for (int mi = 0; mi < 2; mi++)
#pragma unroll
                for (int nj = 0; nj < 4; nj++) {
                    asm volatile(
                        "mma.sync.aligned.m16n8k8.row.col.f32.tf32.tf32.f32 "
                        "{%0,%1,%2,%3}, {%4,%5,%6,%7}, {%8,%9}, {%0,%1,%2,%3};"
                        : "+f"(acc[mi][nj][0]), "+f"(acc[mi][nj][1]),
                          "+f"(acc[mi][nj][2]), "+f"(acc[mi][nj][3])
                        : "r"(af[mi][0]), "r"(af[mi][1]), "r"(af[mi][2]), "r"(af[mi][3]),
                          "r"(bf[nj][0]), "r"(bf[nj][1]));
                }
        }
        __syncthreads();
    }

    // epilogue: two float2 stores per tile
#pragma unroll
    for (int mi = 0; mi < 2; mi++) {
        int rbase = m0 + wm * 32 + mi * 16 + g;
#pragma unroll
        for (int nj = 0; nj < 4; nj++) {
            int col = n0 + wn * 32 + nj * 8 + 2 * tg;
            if (col < N) {
                *(float2*)(C + (size_t)rbase * N + col) =
                    make_float2(acc[mi][nj][0], acc[mi][nj][1]);
                *(float2*)(C + (size_t)(rbase + 8) * N + col) =
                    make_float2(acc[mi][nj][2], acc[mi][nj][3]);
            }
        }
    }
}

// ---------------- kernel 3: dt = softplus(raw + bias), dA = exp(dt*A) -------
__global__ void dtda_kernel(const float* __restrict__ dt_bias,
                            const float* __restrict__ A_log)
{
    int id = blockIdx.x * blockDim.x + threadIdx.x;
    if (id >= ROWS * NH) return;
    int r = id >> 3, h = id & 7;
    float v = g_zx[(size_t)r * DIN + (DIN - NH) + h] + dt_bias[h];
    float d = (v > 20.f) ? v : log1pf(expf(v));
    float A = -expf(A_log[h]);
    g_dt[id] = d;
    g_da[id] = expf(d * A);
}

// ---------------- kernel 4: conv(4) + SiLU with register history ----------
#define TROW 8
__global__ void conv_kernel(const float* __restrict__ cw,
                            const float* __restrict__ cb)
{
    int id = blockIdx.x * blockDim.x + threadIdx.x;
    if (id >= (ROWS / TROW) * CONVD) return;
    int c  = id % CONVD;
    int rb = id / CONVD;
    int r0 = rb * TROW;
    int l0 = r0 & (LSEQ - 1);

    const float* col = g_zx + DINNER + c;   // row stride DIN
    float w0 = cw[c * 4 + 0], w1 = cw[c * 4 + 1];
    float w2 = cw[c * 4 + 2], w3 = cw[c * 4 + 3];
    float bias = cb[c];

    // history (zero at sequence start; chunks never straddle since TROW|LSEQ)
    float vm3 = 0.f, vm2 = 0.f, vm1 = 0.f;
    if (l0 != 0) {
        vm3 = col[(size_t)(r0 - 3) * DIN];
        vm2 = col[(size_t)(r0 - 2) * DIN];
        vm1 = col[(size_t)(r0 - 1) * DIN];
    }
#pragma unroll
    for (int i = 0; i < TROW; i++) {
        float v = col[(size_t)(r0 + i) * DIN];
        float acc = bias + w3 * v + w2 * vm1 + w1 * vm2 + w0 * vm3;
        float sg = 1.f / (1.f + expf(-acc));
        g_xbc[(size_t)(r0 + i) * CONVD + c] = acc * sg;
        vm3 = vm2; vm2 = vm1; vm1 = v;
    }
}

// ---------------- kernel 5a: segment-local scan ----------------
__global__ __launch_bounds__(64) void scanA_kernel(const float* __restrict__ Dp)
{
    const int blk = blockIdx.x;
    const int bh  = blk / SEG;
    const int seg = blk % SEG;
    const int b = bh >> 3, h = bh & 7;
    const int p = threadIdx.x;
    const float Dh = Dp[h];

    float hs[DS];
#pragma unroll
    for (int n = 0; n < DS; n++) hs[n] = 0.f;
    float prod = 1.f;

    const size_t r0 = (size_t)b * LSEQ + seg * SLEN;
    for (int l = 0; l < SLEN; l++) {
        const size_t r = r0 + l;
        const float* base = g_xbc + r * CONVD;
        float dav = g_da[r * NH + h];
        float dtv = g_dt[r * NH + h];
        float xv  = base[h * HD + p];
        prod *= dav;

        float4 B0 = *(const float4*)(base + DINNER +  0);
        float4 B1 = *(const float4*)(base + DINNER +  4);
        float4 B2 = *(const float4*)(base + DINNER +  8);
        float4 B3 = *(const float4*)(base + DINNER + 12);
        float4 C0 = *(const float4*)(base + DINNER + 16);
        float4 C1 = *(const float4*)(base + DINNER + 20);
        float4 C2 = *(const float4*)(base + DINNER + 24);
        float4 C3 = *(const float4*)(base + DINNER + 28);
        float bb[DS] = {B0.x,B0.y,B0.z,B0.w, B1.x,B1.y,B1.z,B1.w,
                        B2.x,B2.y,B2.z,B2.w, B3.x,B3.y,B3.z,B3.w};
        float cc[DS] = {C0.x,C0.y,C0.z,C0.w, C1.x,C1.y,C1.z,C1.w,
                        C2.x,C2.y,C2.z,C2.w, C3.x,C3.y,C3.z,C3.w};

        float t1 = dtv * xv;
        float yv = 0.f;
#pragma unroll
        for (int n = 0; n < DS; n++) {
            hs[n] = fmaf(dav, hs[n], t1 * bb[n]);
            yv = fmaf(hs[n], cc[n], yv);
        }
        g_y[r * DINNER + h * HD + p] = yv + Dh * xv;
    }

    float* he = g_hend + ((size_t)bh * SEG + seg) * STATE + p * DS;
#pragma unroll
    for (int n = 0; n < DS; n += 4)
        *(float4*)(he + n) = make_float4(hs[n], hs[n+1], hs[n+2], hs[n+3]);
    if (p == 0) g_P[(size_t)bh * SEG + seg] = prod;
}

// ---------------- kernel 5b: compose segment states ----------------
__global__ __launch_bounds__(1024) void scanB_kernel()
{
    const int bh = blockIdx.x;
    const int pn = threadIdx.x;
    __shared__ float sP[SEG];
    if (pn < SEG) sP[pn] = g_P[(size_t)bh * SEG + pn];
    __syncthreads();

    float h = 0.f;
    const size_t base = (size_t)bh * SEG * STATE + pn;
    for (int seg = 0; seg < SEG; seg++) {
        g_hin[base + (size_t)seg * STATE] = h;
        h = fmaf(sP[seg], h, g_hend[base + (size_t)seg * STATE]);
    }
}

// ---------------- kernel 5c: cross-segment correction ----------------
__global__ __launch_bounds__(64) void scanC_kernel()
{
    const int blk = blockIdx.x;
    const int bh  = blk / (SEG - 1);
    const int seg = blk % (SEG - 1) + 1;
    const int b = bh >> 3, h = bh & 7;
    const int p = threadIdx.x;

    float hi[DS];
    const float* hp = g_hin + ((size_t)bh * SEG + seg) * STATE + p * DS;
#pragma unroll
    for (int n = 0; n < DS; n += 4) {
        float4 v = *(const float4*)(hp + n);
        hi[n] = v.x; hi[n+1] = v.y; hi[n+2] = v.z; hi[n+3] = v.w;
    }

    float cp = 1.f;
    const size_t r0 = (size_t)b * LSEQ + seg * SLEN;
    for (int l = 0; l < SLEN; l++) {
        const size_t r = r0 + l;
        const float* base = g_xbc + r * CONVD;
        cp *= g_da[r * NH + h];

        float4 C0 = *(const float4*)(base + DINNER + 16);
        float4 C1 = *(const float4*)(base + DINNER + 20);
        float4 C2 = *(const float4*)(base + DINNER + 24);
        float4 C3 = *(const float4*)(base + DINNER + 28);
        float cc[DS] = {C0.x,C0.y,C0.z,C0.w, C1.x,C1.y,C1.z,C1.w,
                        C2.x,C2.y,C2.z,C2.w, C3.x,C3.y,C3.z,C3.w};

        float dot = 0.f;
#pragma unroll
        for (int n = 0; n < DS; n++) dot = fmaf(hi[n], cc[n], dot);
        g_y[r * DINNER + h * HD + p] += cp * dot;
    }
}

// ---------------- kernel 6: gate with silu(z) + RMSNorm ----------------
__global__ __launch_bounds__(256) void gatenorm_kernel(const float* __restrict__ rms_w)
{
    const int r = blockIdx.x;
    const int t = threadIdx.x;
    __shared__ float red[8];

    float vals[2];
    float sum = 0.f;
#pragma unroll
    for (int j = 0; j < 2; j++) {
        int i = t + j * 256;
        float yv = g_y[(size_t)r * DINNER + i];
        float zv = g_zx[(size_t)r * DIN + i];
        float g = zv / (1.f + expf(-zv));
        float v = yv * g;
        vals[j] = v;
        sum += v * v;
    }
#pragma unroll
    for (int o = 16; o; o >>= 1) sum += __shfl_xor_sync(0xffffffffu, sum, o);
    if ((t & 31) == 0) red[t >> 5] = sum;
    __syncthreads();
    if (t < 8) {
        float v = red[t];
#pragma unroll
        for (int o = 4; o; o >>= 1) v += __shfl_xor_sync(0xffu, v, o);
        if (t == 0) red[0] = v;
    }
    __syncthreads();
    float rn = rsqrtf(red[0] * (1.f / (float)DINNER) + EPS);
#pragma unroll
    for (int j = 0; j < 2; j++) {
        int i = t + j * 256;
        g_yn[(size_t)r * DINNER + i] = vals[j] * rn * rms_w[i];
    }
}

// ---------------- kernel 7: transpose (l,c)->(c,l) + residual add ----------
__global__ void trans_add_kernel(const float* __restrict__ x,
                                 float* __restrict__ out)
{
    __shared__ float tile[32][33];
    const int b  = blockIdx.z;
    const int l0 = blockIdx.y * 32;
    const int c0 = blockIdx.x * 32;
    const int tx = threadIdx.x, ty = threadIdx.y;

#pragma unroll
    for (int i = ty; i < 32; i += 8)
        tile[i][tx] = g_o[((size_t)b * LSEQ + l0 + i) * CCH + c0 + tx];
    __syncthreads();
#pragma unroll
    for (int i = ty; i < 32; i += 8) {
        size_t o = ((size_t)b * CCH + c0 + i) * LSEQ + l0 + tx;
        out[o] = tile[tx][i] + x[o];
    }
}

extern "C" void kernel_launch(void* const* d_in, const int* in_sizes, int n_in,
                              void* d_out, int out_size)
{
    const float* x       = (const float*)d_in[0];
    const float* ln_g    = (const float*)d_in[1];
    const float* ln_b    = (const float*)d_in[2];
    const float* Win     = (const float*)d_in[3];
    const float* Wout    = (const float*)d_in[4];
    const float* conv_w  = (const float*)d_in[5];
    const float* conv_b  = (const float*)d_in[6];
    const float* dt_bias = (const float*)d_in[7];
    const float* A_log   = (const float*)d_in[8];
    const float* Dp      = (const float*)d_in[9];
    const float* rms_w   = (const float*)d_in[10];
    float* out = (float*)d_out;

    static float *p_un = nullptr, *p_zx, *p_yn, *p_o;
    if (!p_un) {
        cudaGetSymbolAddress((void**)&p_un, g_un);
        cudaGetSymbolAddress((void**)&p_zx, g_zx);
        cudaGetSymbolAddress((void**)&p_yn, g_yn);
        cudaGetSymbolAddress((void**)&p_o,  g_o);
    }

    // 1) layernorm
    ln_kernel<<<dim3(LSEQ / 32, BATCH), 256>>>(x, ln_g, ln_b);

    // 2) in_proj GEMM (TF32 TC): (32768x256)@(256x1064)
    gemm_tf32_kernel<<<dim3((DIN + 63) / 64, ROWS / 128), 256>>>(
        p_un, Win, p_zx, ROWS, DIN, CCH);

    // 3) dt / dA
    dtda_kernel<<<(ROWS * NH + 255) / 256, 256>>>(dt_bias, A_log);

    // 4) conv + silu
    conv_kernel<<<((ROWS / TROW) * CONVD + 255) / 256, 256>>>(conv_w, conv_b);

    // 5) segmented SSM scan
    scanA_kernel<<<NBH * SEG, HD>>>(Dp);
    scanB_kernel<<<NBH, STATE>>>();
    scanC_kernel<<<NBH * (SEG - 1), HD>>>();

    // 6) gate + rmsnorm
    gatenorm_kernel<<<ROWS, 256>>>(rms_w);

    // 7) out_proj GEMM (TF32 TC): (32768x512)@(512x256)
    gemm_tf32_kernel<<<dim3(CCH / 64, ROWS / 128), 256>>>(
        p_yn, Wout, p_o, ROWS, CCH, DINNER);

    // 8) transpose + residual
    trans_add_kernel<<<dim3(CCH / 32, LSEQ / 32, BATCH), dim3(32, 8)>>>(x, out);
}

// round 6
// speedup vs baseline: 1.8754x; 1.0792x over previous
#include <cuda_runtime.h>
#include <cuda_bf16.h>
#include <math.h>
#include <stdint.h>

// ---------------- problem constants ----------------
#define BATCH   8
#define CCH     256
#define LSEQ    4096
#define ROWS    (BATCH*LSEQ)   // 32768
#define DIN     1064
#define DINNER  512
#define CONVD   544
#define NH      8
#define HD      64
#define DS      16
#define EPS     1e-5f

#define SEG     64
#define SLEN    (LSEQ/SEG)
#define NBH     (BATCH*NH)
#define STATE   (HD*DS)

// ---------------- scratch ----------------
__device__ float g_un [(size_t)ROWS*CCH];
__device__ float g_zx [(size_t)ROWS*DIN];
__device__ float g_xbc[(size_t)ROWS*CONVD];
__device__ float g_dt [(size_t)ROWS*NH];
__device__ float g_da [(size_t)ROWS*NH];
__device__ float g_y  [(size_t)ROWS*DINNER];
__device__ float g_hend[(size_t)NBH*SEG*STATE];
__device__ float g_hin [(size_t)NBH*SEG*STATE];
__device__ float g_P   [(size_t)NBH*SEG];

// ---------------- helpers ----------------
__device__ __forceinline__ uint32_t f2tf32(float f) {
    uint32_t r;
    asm("cvt.rna.tf32.f32 %0, %1;" : "=r"(r) : "f"(f));
    return r;
}
__device__ __forceinline__ void cp16(float* s, const float* g) {
    uint32_t sa = (uint32_t)__cvta_generic_to_shared(s);
    asm volatile("cp.async.cg.shared.global [%0], [%1], 16;" :: "r"(sa), "l"(g));
}
__device__ __forceinline__ void cp8z(float* s, const float* g, bool p) {
    uint32_t sa = (uint32_t)__cvta_generic_to_shared(s);
    int sz = p ? 8 : 0;
    asm volatile("cp.async.ca.shared.global [%0], [%1], 8, %2;" :: "r"(sa), "l"(g), "r"(sz));
}
#define CP_COMMIT() asm volatile("cp.async.commit_group;")
#define CP_WAIT1()  asm volatile("cp.async.wait_group 1;")

#define MMA_TF32(acc, af, bf) \
    asm volatile( \
        "mma.sync.aligned.m16n8k8.row.col.f32.tf32.tf32.f32 " \
        "{%0,%1,%2,%3}, {%4,%5,%6,%7}, {%8,%9}, {%0,%1,%2,%3};" \
        : "+f"(acc[0]), "+f"(acc[1]), "+f"(acc[2]), "+f"(acc[3]) \
        : "r"(af[0]), "r"(af[1]), "r"(af[2]), "r"(af[3]), "r"(bf[0]), "r"(bf[1]))

// ---------------- kernel 1: layernorm with transpose-read ----------------
__global__ __launch_bounds__(256) void ln_kernel(
    const float* __restrict__ x, const float* __restrict__ gamma,
    const float* __restrict__ beta)
{
    __shared__ float s[256][33];
    __shared__ float s_mu[32], s_rs[32];
    const int b  = blockIdx.y;
    const int l0 = blockIdx.x * 32;
    const int t  = threadIdx.x;

#pragma unroll
    for (int i = 0; i < 32; i++) {
        int flat = i * 256 + t;
        int c  = flat >> 5;
        int lp = flat & 31;
        s[c][lp] = x[((size_t)b * CCH + c) * LSEQ + l0 + lp];
    }
    __syncthreads();

    const int wid = t >> 5, lane = t & 31;
    for (int j = wid; j < 32; j += 8) {
        float v = 0.f, v2 = 0.f;
#pragma unroll
        for (int k = 0; k < 8; k++) {
            float a = s[lane + 32 * k][j];
            v += a; v2 += a * a;
        }
#pragma unroll
        for (int o = 16; o; o >>= 1) {
            v  += __shfl_xor_sync(0xffffffffu, v,  o);
            v2 += __shfl_xor_sync(0xffffffffu, v2, o);
        }
        if (lane == 0) {
            float m = v * (1.f / 256.f);
            s_mu[j] = m;
            s_rs[j] = rsqrtf(v2 * (1.f / 256.f) - m * m + EPS);
        }
    }
    __syncthreads();

#pragma unroll
    for (int i = 0; i < 32; i++) {
        int flat = i * 256 + t;
        int lp = flat >> 8;
        int c  = flat & 255;
        float v = (s[c][lp] - s_mu[lp]) * s_rs[lp] * gamma[c] + beta[c];
        g_un[((size_t)b * LSEQ + l0 + lp) * CCH + c] = v;
    }
}

// ---------------- GEMM1: zx = un(32768x256) @ Win(256x1064), TF32, cp.async 2-stage
// BM=128, BN=128, BK=32. 8 warps (4x2), warp tile 32x64 (2x8 m16n8k8).
#define G1_ASTRIDE 36
#define G1_BSTRIDE 136
#define G1_ASZ (128*G1_ASTRIDE)   // 4608
#define G1_BSZ (32*G1_BSTRIDE)    // 4352
#define SMEM_G1 ((2*G1_ASZ + 2*G1_BSZ)*4)   // 71680 bytes

__global__ __launch_bounds__(256) void gemm1_kernel(const float* __restrict__ Bmat)
{
    extern __shared__ float dsm[];
    float* As = dsm;                  // [2][128][36]
    float* Bs = dsm + 2*G1_ASZ;       // [2][32][136]
    const int t = threadIdx.x;
    const int warp = t >> 5, lane = t & 31;
    const int wm = warp & 3, wn = warp >> 2;
    const int m0 = blockIdx.y * 128;
    const int n0 = blockIdx.x * 128;
    const int g = lane >> 2, tg = lane & 3;
    const int N = DIN, K = CCH;

    float acc[2][8][4];
#pragma unroll
    for (int mi = 0; mi < 2; mi++)
#pragma unroll
        for (int nj = 0; nj < 8; nj++)
#pragma unroll
            for (int q = 0; q < 4; q++) acc[mi][nj][q] = 0.f;

    auto issue = [&](int tile, int buf) {
        const float* Ag = g_un + (size_t)m0 * K + tile * 32;
        float* Asb = As + buf * G1_ASZ;
#pragma unroll
        for (int i = 0; i < 4; i++) {
            int idx = t + i * 256;
            int row = idx >> 3, kc = (idx & 7) << 2;
            cp16(Asb + row * G1_ASTRIDE + kc, Ag + (size_t)row * K + kc);
        }
        const float* Bg = Bmat + (size_t)(tile * 32) * N + n0;
        float* Bsb = Bs + buf * G1_BSZ;
#pragma unroll
        for (int i = 0; i < 8; i++) {
            int idx = t + i * 256;
            int kr = idx >> 6, nc = (idx & 63) << 1;
            cp8z(Bsb + kr * G1_BSTRIDE + nc, Bg + (size_t)kr * N + nc, n0 + nc < N);
        }
    };

    const int T = K / 32;   // 8
    issue(0, 0);
    CP_COMMIT();
    for (int i = 0; i < T; i++) {
        if (i + 1 < T) issue(i + 1, (i + 1) & 1);
        CP_COMMIT();
        CP_WAIT1();
        __syncthreads();
        const float* Asb = As + (i & 1) * G1_ASZ;
        const float* Bsb = Bs + (i & 1) * G1_BSZ;
#pragma unroll
        for (int kk = 0; kk < 32; kk += 8) {
            uint32_t af[2][4];
#pragma unroll
            for (int mi = 0; mi < 2; mi++) {
                int mb = wm * 32 + mi * 16;
                af[mi][0] = f2tf32(Asb[(mb + g    ) * G1_ASTRIDE + kk + tg]);
                af[mi][1] = f2tf32(Asb[(mb + 8 + g) * G1_ASTRIDE + kk + tg]);
                af[mi][2] = f2tf32(Asb[(mb + g    ) * G1_ASTRIDE + kk + 4 + tg]);
                af[mi][3] = f2tf32(Asb[(mb + 8 + g) * G1_ASTRIDE + kk + 4 + tg]);
            }
            uint32_t bf[8][2];
#pragma unroll
            for (int nj = 0; nj < 8; nj++) {
                int nb = wn * 64 + nj * 8;
                bf[nj][0] = f2tf32(Bsb[(kk + tg    ) * G1_BSTRIDE + nb + g]);
                bf[nj][1] = f2tf32(Bsb[(kk + 4 + tg) * G1_BSTRIDE + nb + g]);
            }
#pragma unroll
            for (int mi = 0; mi < 2; mi++)
#pragma unroll
                for (int nj = 0; nj < 8; nj++) MMA_TF32(acc[mi][nj], af[mi], bf[nj]);
        }
        __syncthreads();
    }

#pragma unroll
    for (int mi = 0; mi < 2; mi++) {
        int rbase = m0 + wm * 32 + mi * 16 + g;
#pragma unroll
        for (int nj = 0; nj < 8; nj++) {
            int col = n0 + wn * 64 + nj * 8 + 2 * tg;
            if (col < N) {
                *(float2*)(g_zx + (size_t)rbase * N + col) =
                    make_float2(acc[mi][nj][0], acc[mi][nj][1]);
                *(float2*)(g_zx + (size_t)(rbase + 8) * N + col) =
                    make_float2(acc[mi][nj][2], acc[mi][nj][3]);
            }
        }
    }
}

// ---------------- kernel 3: dt / dA ----------------
__global__ void dtda_kernel(const float* __restrict__ dt_bias,
                            const float* __restrict__ A_log)
{
    int id = blockIdx.x * blockDim.x + threadIdx.x;
    if (id >= ROWS * NH) return;
    int r = id >> 3, h = id & 7;
    float v = g_zx[(size_t)r * DIN + (DIN - NH) + h] + dt_bias[h];
    float d = (v > 20.f) ? v : log1pf(expf(v));
    float A = -expf(A_log[h]);
    g_dt[id] = d;
    g_da[id] = expf(d * A);
}

// ---------------- kernel 4: conv(4) + SiLU with register history ----------
#define TROW 8
__global__ void conv_kernel(const float* __restrict__ cw,
                            const float* __restrict__ cb)
{
    int id = blockIdx.x * blockDim.x + threadIdx.x;
    if (id >= (ROWS / TROW) * CONVD) return;
    int c  = id % CONVD;
    int rb = id / CONVD;
    int r0 = rb * TROW;
    int l0 = r0 & (LSEQ - 1);

    const float* col = g_zx + DINNER + c;
    float w0 = cw[c * 4 + 0], w1 = cw[c * 4 + 1];
    float w2 = cw[c * 4 + 2], w3 = cw[c * 4 + 3];
    float bias = cb[c];

    float vm3 = 0.f, vm2 = 0.f, vm1 = 0.f;
    if (l0 != 0) {
        vm3 = col[(size_t)(r0 - 3) * DIN];
        vm2 = col[(size_t)(r0 - 2) * DIN];
        vm1 = col[(size_t)(r0 - 1) * DIN];
    }
#pragma unroll
    for (int i = 0; i < TROW; i++) {
        float v = col[(size_t)(r0 + i) * DIN];
        float acc = bias + w3 * v + w2 * vm1 + w1 * vm2 + w0 * vm3;
        float sg = 1.f / (1.f + expf(-acc));
        g_xbc[(size_t)(r0 + i) * CONVD + c] = acc * sg;
        vm3 = vm2; vm2 = vm1; vm1 = v;
    }
}

// ---------------- kernel 5a: segment-local scan ----------------
__global__ __launch_bounds__(64) void scanA_kernel(const float* __restrict__ Dp)
{
    const int blk = blockIdx.x;
    const int bh  = blk / SEG;
    const int seg = blk % SEG;
    const int b = bh >> 3, h = bh & 7;
    const int p = threadIdx.x;
    const float Dh = Dp[h];

    float hs[DS];
#pragma unroll
    for (int n = 0; n < DS; n++) hs[n] = 0.f;
    float prod = 1.f;

    const size_t r0 = (size_t)b * LSEQ + seg * SLEN;
    for (int l = 0; l < SLEN; l++) {
        const size_t r = r0 + l;
        const float* base = g_xbc + r * CONVD;
        float dav = g_da[r * NH + h];
        float dtv = g_dt[r * NH + h];
        float xv  = base[h * HD + p];
        prod *= dav;

        float4 B0 = *(const float4*)(base + DINNER +  0);
        float4 B1 = *(const float4*)(base + DINNER +  4);
        float4 B2 = *(const float4*)(base + DINNER +  8);
        float4 B3 = *(const float4*)(base + DINNER + 12);
        float4 C0 = *(const float4*)(base + DINNER + 16);
        float4 C1 = *(const float4*)(base + DINNER + 20);
        float4 C2 = *(const float4*)(base + DINNER + 24);
        float4 C3 = *(const float4*)(base + DINNER + 28);
        float bb[DS] = {B0.x,B0.y,B0.z,B0.w, B1.x,B1.y,B1.z,B1.w,
                        B2.x,B2.y,B2.z,B2.w, B3.x,B3.y,B3.z,B3.w};
        float cc[DS] = {C0.x,C0.y,C0.z,C0.w, C1.x,C1.y,C1.z,C1.w,
                        C2.x,C2.y,C2.z,C2.w, C3.x,C3.y,C3.z,C3.w};

        float t1 = dtv * xv;
        float yv = 0.f;
#pragma unroll
        for (int n = 0; n < DS; n++) {
            hs[n] = fmaf(dav, hs[n], t1 * bb[n]);
            yv = fmaf(hs[n], cc[n], yv);
        }
        g_y[r * DINNER + h * HD + p] = yv + Dh * xv;
    }

    float* he = g_hend + ((size_t)bh * SEG + seg) * STATE + p * DS;
#pragma unroll
    for (int n = 0; n < DS; n += 4)
        *(float4*)(he + n) = make_float4(hs[n], hs[n+1], hs[n+2], hs[n+3]);
    if (p == 0) g_P[(size_t)bh * SEG + seg] = prod;
}

// ---------------- kernel 5b: compose segment states ----------------
__global__ __launch_bounds__(1024) void scanB_kernel()
{
    const int bh = blockIdx.x;
    const int pn = threadIdx.x;
    __shared__ float sP[SEG];
    if (pn < SEG) sP[pn] = g_P[(size_t)bh * SEG + pn];
    __syncthreads();

    float h = 0.f;
    const size_t base = (size_t)bh * SEG * STATE + pn;
    for (int seg = 0; seg < SEG; seg++) {
        g_hin[base + (size_t)seg * STATE] = h;
        h = fmaf(sP[seg], h, g_hend[base + (size_t)seg * STATE]);
    }
}

// ---------------- kernel 5c: cross-segment correction ----------------
__global__ __launch_bounds__(64) void scanC_kernel()
{
    const int blk = blockIdx.x;
    const int bh  = blk / (SEG - 1);
    const int seg = blk % (SEG - 1) + 1;
    const int b = bh >> 3, h = bh & 7;
    const int p = threadIdx.x;

    float hi[DS];
    const float* hp = g_hin + ((size_t)bh * SEG + seg) * STATE + p * DS;
#pragma unroll
    for (int n = 0; n < DS; n += 4) {
        float4 v = *(const float4*)(hp + n);
        hi[n] = v.x; hi[n+1] = v.y; hi[n+2] = v.z; hi[n+3] = v.w;
    }

    float cp = 1.f;
    const size_t r0 = (size_t)b * LSEQ + seg * SLEN;
    for (int l = 0; l < SLEN; l++) {
        const size_t r = r0 + l;
        const float* base = g_xbc + r * CONVD;
        cp *= g_da[r * NH + h];

        float4 C0 = *(const float4*)(base + DINNER + 16);
        float4 C1 = *(const float4*)(base + DINNER + 20);
        float4 C2 = *(const float4*)(base + DINNER + 24);
        float4 C3 = *(const float4*)(base + DINNER + 28);
        float cc[DS] = {C0.x,C0.y,C0.z,C0.w, C1.x,C1.y,C1.z,C1.w,
                        C2.x,C2.y,C2.z,C2.w, C3.x,C3.y,C3.z,C3.w};

        float dot = 0.f;
#pragma unroll
        for (int n = 0; n < DS; n++) dot = fmaf(hi[n], cc[n], dot);
        g_y[r * DINNER + h * HD + p] += cp * dot;
    }
}

// ---------------- GEMM2 fused: gate + RMSNorm + (y'@Wout) + transpose + residual
// BM=64, BN=256 (full N), BK=32. 8 warps (2x4), warp tile 32x64.
#define G2_ASTRIDE 36
#define G2_BSTRIDE 264
#define G2_POOL (64*G2_ASTRIDE + 32*G2_BSTRIDE)   // 10752 floats

__global__ __launch_bounds__(256) void gemm2_fused_kernel(
    const float* __restrict__ Wout, const float* __restrict__ rms_w,
    const float* __restrict__ x, float* __restrict__ out)
{
    __shared__ float pool[G2_POOL];
    float* As = pool;                   // [64][36]
    float* Bs = pool + 64 * G2_ASTRIDE; // [32][264]
    const int t = threadIdx.x;
    const int warp = t >> 5, lane = t & 31;
    const int wm = warp & 1, wn = warp >> 1;
    const int m0 = blockIdx.x * 64;
    const int g = lane >> 2, tg = lane & 3;
    const int r0 = t >> 3, kc0 = (t & 7) << 2;

    float acc[2][8][4];
#pragma unroll
    for (int mi = 0; mi < 2; mi++)
#pragma unroll
        for (int nj = 0; nj < 8; nj++)
#pragma unroll
            for (int q = 0; q < 4; q++) acc[mi][nj][q] = 0.f;
    float sq0 = 0.f, sq1 = 0.f;

    for (int k0 = 0; k0 < DINNER; k0 += 32) {
        // A: v = y * silu(z), track sum of squares
#pragma unroll
        for (int i = 0; i < 2; i++) {
            int row = r0 + i * 32;
            size_t rr = (size_t)(m0 + row);
            float4 yv = *(const float4*)(g_y  + rr * DINNER + k0 + kc0);
            float4 zv = *(const float4*)(g_zx + rr * DIN    + k0 + kc0);
            float v0 = yv.x * (zv.x / (1.f + expf(-zv.x)));
            float v1 = yv.y * (zv.y / (1.f + expf(-zv.y)));
            float v2 = yv.z * (zv.z / (1.f + expf(-zv.z)));
            float v3 = yv.w * (zv.w / (1.f + expf(-zv.w)));
            As[row * G2_ASTRIDE + kc0 + 0] = v0;
            As[row * G2_ASTRIDE + kc0 + 1] = v1;
            As[row * G2_ASTRIDE + kc0 + 2] = v2;
            As[row * G2_ASTRIDE + kc0 + 3] = v3;
            float s = v0*v0 + v1*v1 + v2*v2 + v3*v3;
            if (i == 0) sq0 += s; else sq1 += s;
        }
        // B: Wout row scaled by rms_w[k]
#pragma unroll
        for (int i = 0; i < 8; i++) {
            int idx = t + i * 256;
            int kr = idx >> 6, nc = (idx & 63) << 2;
            float w = rms_w[k0 + kr];
            float4 bv = *(const float4*)(Wout + (size_t)(k0 + kr) * CCH + nc);
            Bs[kr * G2_BSTRIDE + nc + 0] = bv.x * w;
            Bs[kr * G2_BSTRIDE + nc + 1] = bv.y * w;
            Bs[kr * G2_BSTRIDE + nc + 2] = bv.z * w;
            Bs[kr * G2_BSTRIDE + nc + 3] = bv.w * w;
        }
        __syncthreads();
#pragma unroll
        for (int kk = 0; kk < 32; kk += 8) {
            uint32_t af[2][4];
#pragma unroll
            for (int mi = 0; mi < 2; mi++) {
                int mb = wm * 32 + mi * 16;
                af[mi][0] = f2tf32(As[(mb + g    ) * G2_ASTRIDE + kk + tg]);
                af[mi][1] = f2tf32(As[(mb + 8 + g) * G2_ASTRIDE + kk + tg]);
                af[mi][2] = f2tf32(As[(mb + g    ) * G2_ASTRIDE + kk + 4 + tg]);
                af[mi][3] = f2tf32(As[(mb + 8 + g) * G2_ASTRIDE + kk + 4 + tg]);
            }
            uint32_t bf[8][2];
#pragma unroll
            for (int nj = 0; nj < 8; nj++) {
                int nb = wn * 64 + nj * 8;
                bf[nj][0] = f2tf32(Bs[(kk + tg    ) * G2_BSTRIDE + nb + g]);
                bf[nj][1] = f2tf32(Bs[(kk + 4 + tg) * G2_BSTRIDE + nb + g]);
            }
#pragma unroll
            for (int mi = 0; mi < 2; mi++)
#pragma unroll
                for (int nj = 0; nj < 8; nj++) MMA_TF32(acc[mi][nj], af[mi], bf[nj]);
        }
        __syncthreads();
    }

    // rn reduction (pool reused; k-loop done)
    float* sq = pool;
    sq[r0 * 8 + (t & 7)] = sq0;
    sq[(r0 + 32) * 8 + (t & 7)] = sq1;
    __syncthreads();
    float* rn = pool + 512;
    if (t < 64) {
        float s = 0.f;
#pragma unroll
        for (int j = 0; j < 8; j++) s += sq[t * 8 + j];
        rn[t] = rsqrtf(s * (1.f / (float)DINNER) + EPS);
    }
    __syncthreads();
    float rsc[2][2];
#pragma unroll
    for (int mi = 0; mi < 2; mi++) {
        rsc[mi][0] = rn[wm * 32 + mi * 16 + g];
        rsc[mi][1] = rn[wm * 32 + mi * 16 + 8 + g];
    }
    __syncthreads();

    // epilogue: transpose via smem, add residual, write (b,c,l)
    float* epi = pool;   // [64 cols][stride 68] per chunk
    const int b  = m0 >> 12;
    const int l0 = m0 & (LSEQ - 1);
#pragma unroll
    for (int cj = 0; cj < 4; cj++) {
        if (wn == cj) {
#pragma unroll
            for (int mi = 0; mi < 2; mi++)
#pragma unroll
                for (int nj = 0; nj < 8; nj++)
#pragma unroll
                    for (int q = 0; q < 4; q++) {
                        int Rl = wm * 32 + mi * 16 + g + ((q >> 1) << 3);
                        int cl = nj * 8 + 2 * tg + (q & 1);
                        epi[cl * 68 + Rl] = acc[mi][nj][q] * rsc[mi][q >> 1];
                    }
        }
        __syncthreads();
        {
            int c = t >> 2, seg = t & 3;
            size_t ob = ((size_t)b * CCH + cj * 64 + c) * LSEQ + l0 + seg * 16;
#pragma unroll
            for (int j = 0; j < 4; j++) {
                float4 e  = *(float4*)(epi + c * 68 + seg * 16 + j * 4);
                float4 xr = *(const float4*)(x + ob + j * 4);
                e.x += xr.x; e.y += xr.y; e.z += xr.z; e.w += xr.w;
                *(float4*)(out + ob + j * 4) = e;
            }
        }
        __syncthreads();
    }
}

extern "C" void kernel_launch(void* const* d_in, const int* in_sizes, int n_in,
                              void* d_out, int out_size)
{
    const float* x       = (const float*)d_in[0];
    const float* ln_g    = (const float*)d_in[1];
    const float* ln_b    = (const float*)d_in[2];
    const float* Win     = (const float*)d_in[3];
    const float* Wout    = (const float*)d_in[4];
    const float* conv_w  = (const float*)d_in[5];
    const float* conv_b  = (const float*)d_in[6];
    const float* dt_bias = (const float*)d_in[7];
    const float* A_log   = (const float*)d_in[8];
    const float* Dp      = (const float*)d_in[9];
    const float* rms_w   = (const float*)d_in[10];
    float* out = (float*)d_out;

    // unconditional every call: no static guards (harness rule), idempotent,
    // non-stream API — safe during graph capture.
    cudaFuncSetAttribute(gemm1_kernel,
                         cudaFuncAttributeMaxDynamicSharedMemorySize, SMEM_G1);

    // 1) layernorm
    ln_kernel<<<dim3(LSEQ / 32, BATCH), 256>>>(x, ln_g, ln_b);

    // 2) in_proj GEMM (TF32, cp.async 2-stage)
    gemm1_kernel<<<dim3((DIN + 127) / 128, ROWS / 128), 256, SMEM_G1>>>(Win);

    // 3) dt / dA
    dtda_kernel<<<(ROWS * NH + 255) / 256, 256>>>(dt_bias, A_log);

    // 4) conv + silu
    conv_kernel<<<((ROWS / TROW) * CONVD + 255) / 256, 256>>>(conv_w, conv_b);

    // 5) segmented SSM scan
    scanA_kernel<<<NBH * SEG, HD>>>(Dp);
    scanB_kernel<<<NBH, STATE>>>();
    scanC_kernel<<<NBH * (SEG - 1), HD>>>();

    // 6+7+8) fused: gate + rmsnorm + out_proj + transpose + residual
    gemm2_fused_kernel<<<ROWS / 64, 256>>>(Wout, rms_w, x, out);
}

// round 7
// speedup vs baseline: 1.9658x; 1.0482x over previous
#include <cuda_runtime.h>
#include <cuda_bf16.h>
#include <math.h>
#include <stdint.h>

// ---------------- problem constants ----------------
#define BATCH   8
#define CCH     256
#define LSEQ    4096
#define ROWS    (BATCH*LSEQ)   // 32768
#define DIN     1064
#define DINNER  512
#define CONVD   544
#define NH      8
#define HD      64
#define DS      16
#define EPS     1e-5f

#define SEG     64
#define SLEN    (LSEQ/SEG)
#define NBH     (BATCH*NH)
#define STATE   (HD*DS)

// ---------------- scratch ----------------
__device__ float g_un [(size_t)ROWS*CCH];
__device__ float g_win[(size_t)CCH*DIN];      // TF32-rounded Win
__device__ float g_zx [(size_t)ROWS*DIN];
__device__ float g_xbc[(size_t)ROWS*CONVD];   // only B/C cols [512,544) used
__device__ float g_dt [(size_t)ROWS*NH];
__device__ float g_da [(size_t)ROWS*NH];
__device__ float g_y  [(size_t)ROWS*DINNER];
__device__ float g_hend[(size_t)NBH*SEG*STATE];
__device__ float g_hin [(size_t)NBH*SEG*STATE];
__device__ float g_P   [(size_t)NBH*SEG];

// ---------------- helpers ----------------
__device__ __forceinline__ uint32_t f2tf32(float f) {
    uint32_t r;
    asm("cvt.rna.tf32.f32 %0, %1;" : "=r"(r) : "f"(f));
    return r;
}
__device__ __forceinline__ void cp16(float* s, const float* g) {
    uint32_t sa = (uint32_t)__cvta_generic_to_shared(s);
    asm volatile("cp.async.cg.shared.global [%0], [%1], 16;" :: "r"(sa), "l"(g));
}
__device__ __forceinline__ void cp8z(float* s, const float* g, bool p) {
    uint32_t sa = (uint32_t)__cvta_generic_to_shared(s);
    int sz = p ? 8 : 0;
    asm volatile("cp.async.ca.shared.global [%0], [%1], 8, %2;" :: "r"(sa), "l"(g), "r"(sz));
}
#define CP_COMMIT() asm volatile("cp.async.commit_group;")
#define CP_WAIT1()  asm volatile("cp.async.wait_group 1;")

#define MMA_TF32(acc, af, bf) \
    asm volatile( \
        "mma.sync.aligned.m16n8k8.row.col.f32.tf32.tf32.f32 " \
        "{%0,%1,%2,%3}, {%4,%5,%6,%7}, {%8,%9}, {%0,%1,%2,%3};" \
        : "+f"(acc[0]), "+f"(acc[1]), "+f"(acc[2]), "+f"(acc[3]) \
        : "r"(af[0]), "r"(af[1]), "r"(af[2]), "r"(af[3]), "r"(bf[0]), "r"(bf[1]))

// ---------------- kernel 0: TF32-round Win into scratch ----------------
__global__ void cvtwin_kernel(const float* __restrict__ W)
{
    int i = blockIdx.x * 256 + threadIdx.x;
    if (i < CCH * DIN) g_win[i] = __uint_as_float(f2tf32(W[i]));
}

// ---------------- kernel 1: layernorm (writes TF32-rounded un) ----------
__global__ __launch_bounds__(256) void ln_kernel(
    const float* __restrict__ x, const float* __restrict__ gamma,
    const float* __restrict__ beta)
{
    __shared__ float s[256][33];
    __shared__ float s_mu[32], s_rs[32];
    const int b  = blockIdx.y;
    const int l0 = blockIdx.x * 32;
    const int t  = threadIdx.x;

#pragma unroll
    for (int i = 0; i < 32; i++) {
        int flat = i * 256 + t;
        int c  = flat >> 5;
        int lp = flat & 31;
        s[c][lp] = x[((size_t)b * CCH + c) * LSEQ + l0 + lp];
    }
    __syncthreads();

    const int wid = t >> 5, lane = t & 31;
    for (int j = wid; j < 32; j += 8) {
        float v = 0.f, v2 = 0.f;
#pragma unroll
        for (int k = 0; k < 8; k++) {
            float a = s[lane + 32 * k][j];
            v += a; v2 += a * a;
        }
#pragma unroll
        for (int o = 16; o; o >>= 1) {
            v  += __shfl_xor_sync(0xffffffffu, v,  o);
            v2 += __shfl_xor_sync(0xffffffffu, v2, o);
        }
        if (lane == 0) {
            float m = v * (1.f / 256.f);
            s_mu[j] = m;
            s_rs[j] = rsqrtf(v2 * (1.f / 256.f) - m * m + EPS);
        }
    }
    __syncthreads();

#pragma unroll
    for (int i = 0; i < 32; i++) {
        int flat = i * 256 + t;
        int lp = flat >> 8;
        int c  = flat & 255;
        float v = (s[c][lp] - s_mu[lp]) * s_rs[lp] * gamma[c] + beta[c];
        g_un[((size_t)b * LSEQ + l0 + lp) * CCH + c] = __uint_as_float(f2tf32(v));
    }
}

// ---------------- GEMM1: zx = un @ win, TF32, cp.async 2-stage ----------
// operands pre-rounded -> no cvt in inner loop.
#define G1_ASTRIDE 36
#define G1_BSTRIDE 136
#define G1_ASZ (128*G1_ASTRIDE)
#define G1_BSZ (32*G1_BSTRIDE)
#define SMEM_G1 ((2*G1_ASZ + 2*G1_BSZ)*4)   // 71680 bytes

__global__ __launch_bounds__(256) void gemm1_kernel()
{
    extern __shared__ float dsm[];
    float* As = dsm;
    float* Bs = dsm + 2*G1_ASZ;
    const int t = threadIdx.x;
    const int warp = t >> 5, lane = t & 31;
    const int wm = warp & 3, wn = warp >> 2;
    const int m0 = blockIdx.y * 128;
    const int n0 = blockIdx.x * 128;
    const int g = lane >> 2, tg = lane & 3;
    const int N = DIN, K = CCH;

    float acc[2][8][4];
#pragma unroll
    for (int mi = 0; mi < 2; mi++)
#pragma unroll
        for (int nj = 0; nj < 8; nj++)
#pragma unroll
            for (int q = 0; q < 4; q++) acc[mi][nj][q] = 0.f;

    auto issue = [&](int tile, int buf) {
        const float* Ag = g_un + (size_t)m0 * K + tile * 32;
        float* Asb = As + buf * G1_ASZ;
#pragma unroll
        for (int i = 0; i < 4; i++) {
            int idx = t + i * 256;
            int row = idx >> 3, kc = (idx & 7) << 2;
            cp16(Asb + row * G1_ASTRIDE + kc, Ag + (size_t)row * K + kc);
        }
        const float* Bg = g_win + (size_t)(tile * 32) * N + n0;
        float* Bsb = Bs + buf * G1_BSZ;
#pragma unroll
        for (int i = 0; i < 8; i++) {
            int idx = t + i * 256;
            int kr = idx >> 6, nc = (idx & 63) << 1;
            cp8z(Bsb + kr * G1_BSTRIDE + nc, Bg + (size_t)kr * N + nc, n0 + nc < N);
        }
    };

    const int T = K / 32;   // 8
    issue(0, 0);
    CP_COMMIT();
    for (int i = 0; i < T; i++) {
        if (i + 1 < T) issue(i + 1, (i + 1) & 1);
        CP_COMMIT();
        CP_WAIT1();
        __syncthreads();
        const float* Asb = As + (i & 1) * G1_ASZ;
        const float* Bsb = Bs + (i & 1) * G1_BSZ;
#pragma unroll
        for (int kk = 0; kk < 32; kk += 8) {
            uint32_t af[2][4];
#pragma unroll
            for (int mi = 0; mi < 2; mi++) {
                int mb = wm * 32 + mi * 16;
                af[mi][0] = __float_as_uint(Asb[(mb + g    ) * G1_ASTRIDE + kk + tg]);
                af[mi][1] = __float_as_uint(Asb[(mb + 8 + g) * G1_ASTRIDE + kk + tg]);
                af[mi][2] = __float_as_uint(Asb[(mb + g    ) * G1_ASTRIDE + kk + 4 + tg]);
                af[mi][3] = __float_as_uint(Asb[(mb + 8 + g) * G1_ASTRIDE + kk + 4 + tg]);
            }
            uint32_t bf[8][2];
#pragma unroll
            for (int nj = 0; nj < 8; nj++) {
                int nb = wn * 64 + nj * 8;
                bf[nj][0] = __float_as_uint(Bsb[(kk + tg    ) * G1_BSTRIDE + nb + g]);
                bf[nj][1] = __float_as_uint(Bsb[(kk + 4 + tg) * G1_BSTRIDE + nb + g]);
            }
#pragma unroll
            for (int mi = 0; mi < 2; mi++)
#pragma unroll
                for (int nj = 0; nj < 8; nj++) MMA_TF32(acc[mi][nj], af[mi], bf[nj]);
        }
        __syncthreads();
    }

#pragma unroll
    for (int mi = 0; mi < 2; mi++) {
        int rbase = m0 + wm * 32 + mi * 16 + g;
#pragma unroll
        for (int nj = 0; nj < 8; nj++) {
            int col = n0 + wn * 64 + nj * 8 + 2 * tg;
            if (col < N) {
                *(float2*)(g_zx + (size_t)rbase * N + col) =
                    make_float2(acc[mi][nj][0], acc[mi][nj][1]);
                *(float2*)(g_zx + (size_t)(rbase + 8) * N + col) =
                    make_float2(acc[mi][nj][2], acc[mi][nj][3]);
            }
        }
    }
}

// ---------------- kernel 3: dt / dA ----------------
__global__ void dtda_kernel(const float* __restrict__ dt_bias,
                            const float* __restrict__ A_log)
{
    int id = blockIdx.x * blockDim.x + threadIdx.x;
    if (id >= ROWS * NH) return;
    int r = id >> 3, h = id & 7;
    float v = g_zx[(size_t)r * DIN + (DIN - NH) + h] + dt_bias[h];
    float d = (v > 20.f) ? v : log1pf(expf(v));
    float A = -expf(A_log[h]);
    g_dt[id] = d;
    g_da[id] = expf(d * A);
}

// ---------------- kernel 4: conv(4)+SiLU, B/C channels only ----------
#define TROW 8
#define NBC  32
__global__ void convbc_kernel(const float* __restrict__ cw,
                              const float* __restrict__ cb)
{
    int id = blockIdx.x * blockDim.x + threadIdx.x;
    if (id >= (ROWS / TROW) * NBC) return;
    int c  = DINNER + (id % NBC);     // 512..543
    int rb = id / NBC;
    int r0 = rb * TROW;
    int l0 = r0 & (LSEQ - 1);

    const float* col = g_zx + DINNER + c;
    float w0 = cw[c * 4 + 0], w1 = cw[c * 4 + 1];
    float w2 = cw[c * 4 + 2], w3 = cw[c * 4 + 3];
    float bias = cb[c];

    float vm3 = 0.f, vm2 = 0.f, vm1 = 0.f;
    if (l0 != 0) {
        vm3 = col[(size_t)(r0 - 3) * DIN];
        vm2 = col[(size_t)(r0 - 2) * DIN];
        vm1 = col[(size_t)(r0 - 1) * DIN];
    }
#pragma unroll
    for (int i = 0; i < TROW; i++) {
        float v = col[(size_t)(r0 + i) * DIN];
        float acc = bias + w3 * v + w2 * vm1 + w1 * vm2 + w0 * vm3;
        float sg = 1.f / (1.f + expf(-acc));
        g_xbc[(size_t)(r0 + i) * CONVD + c] = acc * sg;
        vm3 = vm2; vm2 = vm1; vm1 = v;
    }
}

// ---------------- kernel 5a: segment-local scan with fused x-conv -------
__global__ __launch_bounds__(64) void scanA_kernel(
    const float* __restrict__ Dp, const float* __restrict__ cw,
    const float* __restrict__ cb)
{
    const int blk = blockIdx.x;
    const int bh  = blk / SEG;
    const int seg = blk % SEG;
    const int b = bh >> 3, h = bh & 7;
    const int p = threadIdx.x;
    const float Dh = Dp[h];

    // conv params for this thread's x-channel
    const int c = h * HD + p;        // 0..511
    const float w0 = cw[c * 4 + 0], w1 = cw[c * 4 + 1];
    const float w2 = cw[c * 4 + 2], w3 = cw[c * 4 + 3];
    const float cbias = cb[c];
    const float* colz = g_zx + DINNER + c;    // row stride DIN

    float hs[DS];
#pragma unroll
    for (int n = 0; n < DS; n++) hs[n] = 0.f;
    float prod = 1.f;

    const size_t r0 = (size_t)b * LSEQ + seg * SLEN;
    float vm3 = 0.f, vm2 = 0.f, vm1 = 0.f;
    if (seg != 0) {
        vm3 = colz[(r0 - 3) * DIN];
        vm2 = colz[(r0 - 2) * DIN];
        vm1 = colz[(r0 - 1) * DIN];
    }

    for (int l = 0; l < SLEN; l++) {
        const size_t r = r0 + l;
        const float* base = g_xbc + r * CONVD;
        float dav = g_da[r * NH + h];
        float dtv = g_dt[r * NH + h];
        prod *= dav;

        // fused conv + silu for x
        float v = colz[r * DIN];
        float ca = cbias + w3 * v + w2 * vm1 + w1 * vm2 + w0 * vm3;
        float xv = ca / (1.f + expf(-ca));
        vm3 = vm2; vm2 = vm1; vm1 = v;

        float4 B0 = *(const float4*)(base + DINNER +  0);
        float4 B1 = *(const float4*)(base + DINNER +  4);
        float4 B2 = *(const float4*)(base + DINNER +  8);
        float4 B3 = *(const float4*)(base + DINNER + 12);
        float4 C0 = *(const float4*)(base + DINNER + 16);
        float4 C1 = *(const float4*)(base + DINNER + 20);
        float4 C2 = *(const float4*)(base + DINNER + 24);
        float4 C3 = *(const float4*)(base + DINNER + 28);
        float bb[DS] = {B0.x,B0.y,B0.z,B0.w, B1.x,B1.y,B1.z,B1.w,
                        B2.x,B2.y,B2.z,B2.w, B3.x,B3.y,B3.z,B3.w};
        float cc[DS] = {C0.x,C0.y,C0.z,C0.w, C1.x,C1.y,C1.z,C1.w,
                        C2.x,C2.y,C2.z,C2.w, C3.x,C3.y,C3.z,C3.w};

        float t1 = dtv * xv;
        float yv = 0.f;
#pragma unroll
        for (int n = 0; n < DS; n++) {
            hs[n] = fmaf(dav, hs[n], t1 * bb[n]);
            yv = fmaf(hs[n], cc[n], yv);
        }
        g_y[r * DINNER + h * HD + p] = yv + Dh * xv;
    }

    float* he = g_hend + ((size_t)bh * SEG + seg) * STATE + p * DS;
#pragma unroll
    for (int n = 0; n < DS; n += 4)
        *(float4*)(he + n) = make_float4(hs[n], hs[n+1], hs[n+2], hs[n+3]);
    if (p == 0) g_P[(size_t)bh * SEG + seg] = prod;
}

// ---------------- kernel 5b: compose segment states ----------------
__global__ __launch_bounds__(1024) void scanB_kernel()
{
    const int bh = blockIdx.x;
    const int pn = threadIdx.x;
    __shared__ float sP[SEG];
    if (pn < SEG) sP[pn] = g_P[(size_t)bh * SEG + pn];
    __syncthreads();

    float h = 0.f;
    const size_t base = (size_t)bh * SEG * STATE + pn;
    for (int seg = 0; seg < SEG; seg++) {
        g_hin[base + (size_t)seg * STATE] = h;
        h = fmaf(sP[seg], h, g_hend[base + (size_t)seg * STATE]);
    }
}

// ---------------- kernel 5c: cross-segment correction ----------------
__global__ __launch_bounds__(64) void scanC_kernel()
{
    const int blk = blockIdx.x;
    const int bh  = blk / (SEG - 1);
    const int seg = blk % (SEG - 1) + 1;
    const int b = bh >> 3, h = bh & 7;
    const int p = threadIdx.x;

    float hi[DS];
    const float* hp = g_hin + ((size_t)bh * SEG + seg) * STATE + p * DS;
#pragma unroll
    for (int n = 0; n < DS; n += 4) {
        float4 v = *(const float4*)(hp + n);
        hi[n] = v.x; hi[n+1] = v.y; hi[n+2] = v.z; hi[n+3] = v.w;
    }

    float cp = 1.f;
    const size_t r0 = (size_t)b * LSEQ + seg * SLEN;
    for (int l = 0; l < SLEN; l++) {
        const size_t r = r0 + l;
        const float* base = g_xbc + r * CONVD;
        cp *= g_da[r * NH + h];

        float4 C0 = *(const float4*)(base + DINNER + 16);
        float4 C1 = *(const float4*)(base + DINNER + 20);
        float4 C2 = *(const float4*)(base + DINNER + 24);
        float4 C3 = *(const float4*)(base + DINNER + 28);
        float cc[DS] = {C0.x,C0.y,C0.z,C0.w, C1.x,C1.y,C1.z,C1.w,
                        C2.x,C2.y,C2.z,C2.w, C3.x,C3.y,C3.z,C3.w};

        float dot = 0.f;
#pragma unroll
        for (int n = 0; n < DS; n++) dot = fmaf(hi[n], cc[n], dot);
        g_y[r * DINNER + h * HD + p] += cp * dot;
    }
}

// ---------------- GEMM2 fused: gate + RMSNorm + out_proj + transpose + residual
// cvt at fill; inner loop pure LDS+MMA.
#define G2_ASTRIDE 36
#define G2_BSTRIDE 264
#define G2_POOL (64*G2_ASTRIDE + 32*G2_BSTRIDE)

__global__ __launch_bounds__(256) void gemm2_fused_kernel(
    const float* __restrict__ Wout, const float* __restrict__ rms_w,
    const float* __restrict__ x, float* __restrict__ out)
{
    __shared__ float pool[G2_POOL];
    float* As = pool;
    float* Bs = pool + 64 * G2_ASTRIDE;
    const int t = threadIdx.x;
    const int warp = t >> 5, lane = t & 31;
    const int wm = warp & 1, wn = warp >> 1;
    const int m0 = blockIdx.x * 64;
    const int g = lane >> 2, tg = lane & 3;
    const int r0 = t >> 3, kc0 = (t & 7) << 2;

    float acc[2][8][4];
#pragma unroll
    for (int mi = 0; mi < 2; mi++)
#pragma unroll
        for (int nj = 0; nj < 8; nj++)
#pragma unroll
            for (int q = 0; q < 4; q++) acc[mi][nj][q] = 0.f;
    float sq0 = 0.f, sq1 = 0.f;

    for (int k0 = 0; k0 < DINNER; k0 += 32) {
#pragma unroll
        for (int i = 0; i < 2; i++) {
            int row = r0 + i * 32;
            size_t rr = (size_t)(m0 + row);
            float4 yv = *(const float4*)(g_y  + rr * DINNER + k0 + kc0);
            float4 zv = *(const float4*)(g_zx + rr * DIN    + k0 + kc0);
            float v0 = yv.x * (zv.x / (1.f + expf(-zv.x)));
            float v1 = yv.y * (zv.y / (1.f + expf(-zv.y)));
            float v2 = yv.z * (zv.z / (1.f + expf(-zv.z)));
            float v3 = yv.w * (zv.w / (1.f + expf(-zv.w)));
            As[row * G2_ASTRIDE + kc0 + 0] = __uint_as_float(f2tf32(v0));
            As[row * G2_ASTRIDE + kc0 + 1] = __uint_as_float(f2tf32(v1));
            As[row * G2_ASTRIDE + kc0 + 2] = __uint_as_float(f2tf32(v2));
            As[row * G2_ASTRIDE + kc0 + 3] = __uint_as_float(f2tf32(v3));
            float s = v0*v0 + v1*v1 + v2*v2 + v3*v3;
            if (i == 0) sq0 += s; else sq1 += s;
        }
#pragma unroll
        for (int i = 0; i < 8; i++) {
            int idx = t + i * 256;
            int kr = idx >> 6, nc = (idx & 63) << 2;
            float w = rms_w[k0 + kr];
            float4 bv = *(const float4*)(Wout + (size_t)(k0 + kr) * CCH + nc);
            Bs[kr * G2_BSTRIDE + nc + 0] = __uint_as_float(f2tf32(bv.x * w));
            Bs[kr * G2_BSTRIDE + nc + 1] = __uint_as_float(f2tf32(bv.y * w));
            Bs[kr * G2_BSTRIDE + nc + 2] = __uint_as_float(f2tf32(bv.z * w));
            Bs[kr * G2_BSTRIDE + nc + 3] = __uint_as_float(f2tf32(bv.w * w));
        }
        __syncthreads();
#pragma unroll
        for (int kk = 0; kk < 32; kk += 8) {
            uint32_t af[2][4];
#pragma unroll
            for (int mi = 0; mi < 2; mi++) {
                int mb = wm * 32 + mi * 16;
                af[mi][0] = __float_as_uint(As[(mb + g    ) * G2_ASTRIDE + kk + tg]);
                af[mi][1] = __float_as_uint(As[(mb + 8 + g) * G2_ASTRIDE + kk + tg]);
                af[mi][2] = __float_as_uint(As[(mb + g    ) * G2_ASTRIDE + kk + 4 + tg]);
                af[mi][3] = __float_as_uint(As[(mb + 8 + g) * G2_ASTRIDE + kk + 4 + tg]);
            }
            uint32_t bf[8][2];
#pragma unroll
            for (int nj = 0; nj < 8; nj++) {
                int nb = wn * 64 + nj * 8;
                bf[nj][0] = __float_as_uint(Bs[(kk + tg    ) * G2_BSTRIDE + nb + g]);
                bf[nj][1] = __float_as_uint(Bs[(kk + 4 + tg) * G2_BSTRIDE + nb + g]);
            }
#pragma unroll
            for (int mi = 0; mi < 2; mi++)
#pragma unroll
                for (int nj = 0; nj < 8; nj++) MMA_TF32(acc[mi][nj], af[mi], bf[nj]);
        }
        __syncthreads();
    }

    // rn reduction
    float* sq = pool;
    sq[r0 * 8 + (t & 7)] = sq0;
    sq[(r0 + 32) * 8 + (t & 7)] = sq1;
    __syncthreads();
    float* rn = pool + 512;
    if (t < 64) {
        float s = 0.f;
#pragma unroll
        for (int j = 0; j < 8; j++) s += sq[t * 8 + j];
        rn[t] = rsqrtf(s * (1.f / (float)DINNER) + EPS);
    }
    __syncthreads();
    float rsc[2][2];
#pragma unroll
    for (int mi = 0; mi < 2; mi++) {
        rsc[mi][0] = rn[wm * 32 + mi * 16 + g];
        rsc[mi][1] = rn[wm * 32 + mi * 16 + 8 + g];
    }
    __syncthreads();

    // epilogue: transpose + residual
    float* epi = pool;
    const int b  = m0 >> 12;
    const int l0 = m0 & (LSEQ - 1);
#pragma unroll
    for (int cj = 0; cj < 4; cj++) {
        if (wn == cj) {
#pragma unroll
            for (int mi = 0; mi < 2; mi++)
#pragma unroll
                for (int nj = 0; nj < 8; nj++)
#pragma unroll
                    for (int q = 0; q < 4; q++) {
                        int Rl = wm * 32 + mi * 16 + g + ((q >> 1) << 3);
                        int cl = nj * 8 + 2 * tg + (q & 1);
                        epi[cl * 68 + Rl] = acc[mi][nj][q] * rsc[mi][q >> 1];
                    }
        }
        __syncthreads();
        {
            int c = t >> 2, seg = t & 3;
            size_t ob = ((size_t)b * CCH + cj * 64 + c) * LSEQ + l0 + seg * 16;
#pragma unroll
            for (int j = 0; j < 4; j++) {
                float4 e  = *(float4*)(epi + c * 68 + seg * 16 + j * 4);
                float4 xr = *(const float4*)(x + ob + j * 4);
                e.x += xr.x; e.y += xr.y; e.z += xr.z; e.w += xr.w;
                *(float4*)(out + ob + j * 4) = e;
            }
        }
        __syncthreads();
    }
}

extern "C" void kernel_launch(void* const* d_in, const int* in_sizes, int n_in,
                              void* d_out, int out_size)
{
    const float* x       = (const float*)d_in[0];
    const float* ln_g    = (const float*)d_in[1];
    const float* ln_b    = (const float*)d_in[2];
    const float* Win     = (const float*)d_in[3];
    const float* Wout    = (const float*)d_in[4];
    const float* conv_w  = (const float*)d_in[5];
    const float* conv_b  = (const float*)d_in[6];
    const float* dt_bias = (const float*)d_in[7];
    const float* A_log   = (const float*)d_in[8];
    const float* Dp      = (const float*)d_in[9];
    const float* rms_w   = (const float*)d_in[10];
    float* out = (float*)d_out;

    cudaFuncSetAttribute(gemm1_kernel,
                         cudaFuncAttributeMaxDynamicSharedMemorySize, SMEM_G1);

    // 0) TF32-round Win
    cvtwin_kernel<<<(CCH * DIN + 255) / 256, 256>>>(Win);

    // 1) layernorm (writes pre-rounded un)
    ln_kernel<<<dim3(LSEQ / 32, BATCH), 256>>>(x, ln_g, ln_b);

    // 2) in_proj GEMM
    gemm1_kernel<<<dim3((DIN + 127) / 128, ROWS / 128), 256, SMEM_G1>>>();

    // 3) dt / dA
    dtda_kernel<<<(ROWS * NH + 255) / 256, 256>>>(dt_bias, A_log);

    // 4) conv + silu, B/C channels only
    convbc_kernel<<<((ROWS / TROW) * NBC + 255) / 256, 256>>>(conv_w, conv_b);

    // 5) segmented SSM scan (x-conv fused into scanA)
    scanA_kernel<<<NBH * SEG, HD>>>(Dp, conv_w, conv_b);
    scanB_kernel<<<NBH, STATE>>>();
    scanC_kernel<<<NBH * (SEG - 1), HD>>>();

    // 6+7+8) fused: gate + rmsnorm + out_proj + transpose + residual
    gemm2_fused_kernel<<<ROWS / 64, 256>>>(Wout, rms_w, x, out);
}

// round 8
// speedup vs baseline: 2.3441x; 1.1925x over previous
#include <cuda_runtime.h>
#include <cuda_bf16.h>
#include <math.h>
#include <stdint.h>

// ---------------- problem constants ----------------
#define BATCH   8
#define CCH     256
#define LSEQ    4096
#define ROWS    (BATCH*LSEQ)   // 32768
#define DIN     1064
#define DINNER  512
#define CONVD   544
#define NH      8
#define HD      64
#define DS      16
#define EPS     1e-5f

#define SEG     64
#define SLEN    (LSEQ/SEG)
#define NBH     (BATCH*NH)
#define STATE   (HD*DS)

// ---------------- scratch ----------------
__device__ float g_un [(size_t)ROWS*CCH];
__device__ float g_win[(size_t)CCH*DIN];        // TF32-rounded Win
__device__ float g_wouts[(size_t)DINNER*CCH];   // TF32-rounded Wout*rms_w
__device__ float g_zx [(size_t)ROWS*DIN];
__device__ float g_xbc[(size_t)ROWS*CONVD];     // only B/C cols [512,544) used
__device__ float g_dt [(size_t)ROWS*NH];
__device__ float g_da [(size_t)ROWS*NH];
__device__ float g_y  [(size_t)ROWS*DINNER];
__device__ float g_hend[(size_t)NBH*SEG*STATE];
__device__ float g_hin [(size_t)NBH*SEG*STATE];
__device__ float g_P   [(size_t)NBH*SEG];

// ---------------- helpers ----------------
__device__ __forceinline__ uint32_t f2tf32(float f) {
    uint32_t r;
    asm("cvt.rna.tf32.f32 %0, %1;" : "=r"(r) : "f"(f));
    return r;
}
__device__ __forceinline__ float fsig(float v) {   // fast sigmoid
    return __fdividef(1.f, 1.f + __expf(-v));
}
__device__ __forceinline__ void cp16(float* s, const float* g) {
    uint32_t sa = (uint32_t)__cvta_generic_to_shared(s);
    asm volatile("cp.async.cg.shared.global [%0], [%1], 16;" :: "r"(sa), "l"(g));
}
__device__ __forceinline__ void cp8z(float* s, const float* g, bool p) {
    uint32_t sa = (uint32_t)__cvta_generic_to_shared(s);
    int sz = p ? 8 : 0;
    asm volatile("cp.async.ca.shared.global [%0], [%1], 8, %2;" :: "r"(sa), "l"(g), "r"(sz));
}
#define CP_COMMIT() asm volatile("cp.async.commit_group;")
#define CP_WAIT1()  asm volatile("cp.async.wait_group 1;")

#define MMA_TF32(acc, af, bf) \
    asm volatile( \
        "mma.sync.aligned.m16n8k8.row.col.f32.tf32.tf32.f32 " \
        "{%0,%1,%2,%3}, {%4,%5,%6,%7}, {%8,%9}, {%0,%1,%2,%3};" \
        : "+f"(acc[0]), "+f"(acc[1]), "+f"(acc[2]), "+f"(acc[3]) \
        : "r"(af[0]), "r"(af[1]), "r"(af[2]), "r"(af[3]), "r"(bf[0]), "r"(bf[1]))

// ---------------- kernel 0: precompute TF32 weights ----------------
__global__ void prep_kernel(const float* __restrict__ Win,
                            const float* __restrict__ Wout,
                            const float* __restrict__ rms_w)
{
    int i = blockIdx.x * 256 + threadIdx.x;
    if (i < CCH * DIN) g_win[i] = __uint_as_float(f2tf32(Win[i]));
    if (i < DINNER * CCH) {
        int k = i >> 8;
        g_wouts[i] = __uint_as_float(f2tf32(Wout[i] * rms_w[k]));
    }
}

// ---------------- kernel 1: layernorm (writes TF32-rounded un) ----------
__global__ __launch_bounds__(256) void ln_kernel(
    const float* __restrict__ x, const float* __restrict__ gamma,
    const float* __restrict__ beta)
{
    __shared__ float s[256][33];
    __shared__ float s_mu[32], s_rs[32];
    const int b  = blockIdx.y;
    const int l0 = blockIdx.x * 32;
    const int t  = threadIdx.x;

#pragma unroll
    for (int i = 0; i < 32; i++) {
        int flat = i * 256 + t;
        int c  = flat >> 5;
        int lp = flat & 31;
        s[c][lp] = x[((size_t)b * CCH + c) * LSEQ + l0 + lp];
    }
    __syncthreads();

    const int wid = t >> 5, lane = t & 31;
    for (int j = wid; j < 32; j += 8) {
        float v = 0.f, v2 = 0.f;
#pragma unroll
        for (int k = 0; k < 8; k++) {
            float a = s[lane + 32 * k][j];
            v += a; v2 += a * a;
        }
#pragma unroll
        for (int o = 16; o; o >>= 1) {
            v  += __shfl_xor_sync(0xffffffffu, v,  o);
            v2 += __shfl_xor_sync(0xffffffffu, v2, o);
        }
        if (lane == 0) {
            float m = v * (1.f / 256.f);
            s_mu[j] = m;
            s_rs[j] = rsqrtf(v2 * (1.f / 256.f) - m * m + EPS);
        }
    }
    __syncthreads();

#pragma unroll
    for (int i = 0; i < 32; i++) {
        int flat = i * 256 + t;
        int lp = flat >> 8;
        int c  = flat & 255;
        float v = (s[c][lp] - s_mu[lp]) * s_rs[lp] * gamma[c] + beta[c];
        g_un[((size_t)b * LSEQ + l0 + lp) * CCH + c] = __uint_as_float(f2tf32(v));
    }
}

// ---------------- GEMM1: zx = un @ win, TF32, cp.async 2-stage ----------
#define G1_ASTRIDE 36
#define G1_BSTRIDE 136
#define G1_ASZ (128*G1_ASTRIDE)
#define G1_BSZ (32*G1_BSTRIDE)
#define SMEM_G1 ((2*G1_ASZ + 2*G1_BSZ)*4)   // 71680 bytes

__global__ __launch_bounds__(256) void gemm1_kernel()
{
    extern __shared__ float dsm[];
    float* As = dsm;
    float* Bs = dsm + 2*G1_ASZ;
    const int t = threadIdx.x;
    const int warp = t >> 5, lane = t & 31;
    const int wm = warp & 3, wn = warp >> 2;
    const int m0 = blockIdx.y * 128;
    const int n0 = blockIdx.x * 128;
    const int g = lane >> 2, tg = lane & 3;
    const int N = DIN, K = CCH;

    float acc[2][8][4];
#pragma unroll
    for (int mi = 0; mi < 2; mi++)
#pragma unroll
        for (int nj = 0; nj < 8; nj++)
#pragma unroll
            for (int q = 0; q < 4; q++) acc[mi][nj][q] = 0.f;

    auto issue = [&](int tile, int buf) {
        const float* Ag = g_un + (size_t)m0 * K + tile * 32;
        float* Asb = As + buf * G1_ASZ;
#pragma unroll
        for (int i = 0; i < 4; i++) {
            int idx = t + i * 256;
            int row = idx >> 3, kc = (idx & 7) << 2;
            cp16(Asb + row * G1_ASTRIDE + kc, Ag + (size_t)row * K + kc);
        }
        const float* Bg = g_win + (size_t)(tile * 32) * N + n0;
        float* Bsb = Bs + buf * G1_BSZ;
#pragma unroll
        for (int i = 0; i < 8; i++) {
            int idx = t + i * 256;
            int kr = idx >> 6, nc = (idx & 63) << 1;
            cp8z(Bsb + kr * G1_BSTRIDE + nc, Bg + (size_t)kr * N + nc, n0 + nc < N);
        }
    };

    const int T = K / 32;   // 8
    issue(0, 0);
    CP_COMMIT();
    for (int i = 0; i < T; i++) {
        if (i + 1 < T) issue(i + 1, (i + 1) & 1);
        CP_COMMIT();
        CP_WAIT1();
        __syncthreads();
        const float* Asb = As + (i & 1) * G1_ASZ;
        const float* Bsb = Bs + (i & 1) * G1_BSZ;
#pragma unroll
        for (int kk = 0; kk < 32; kk += 8) {
            uint32_t af[2][4];
#pragma unroll
            for (int mi = 0; mi < 2; mi++) {
                int mb = wm * 32 + mi * 16;
                af[mi][0] = __float_as_uint(Asb[(mb + g    ) * G1_ASTRIDE + kk + tg]);
                af[mi][1] = __float_as_uint(Asb[(mb + 8 + g) * G1_ASTRIDE + kk + tg]);
                af[mi][2] = __float_as_uint(Asb[(mb + g    ) * G1_ASTRIDE + kk + 4 + tg]);
                af[mi][3] = __float_as_uint(Asb[(mb + 8 + g) * G1_ASTRIDE + kk + 4 + tg]);
            }
            uint32_t bf[8][2];
#pragma unroll
            for (int nj = 0; nj < 8; nj++) {
                int nb = wn * 64 + nj * 8;
                bf[nj][0] = __float_as_uint(Bsb[(kk + tg    ) * G1_BSTRIDE + nb + g]);
                bf[nj][1] = __float_as_uint(Bsb[(kk + 4 + tg) * G1_BSTRIDE + nb + g]);
            }
#pragma unroll
            for (int mi = 0; mi < 2; mi++)
#pragma unroll
                for (int nj = 0; nj < 8; nj++) MMA_TF32(acc[mi][nj], af[mi], bf[nj]);
        }
        __syncthreads();
    }

#pragma unroll
    for (int mi = 0; mi < 2; mi++) {
        int rbase = m0 + wm * 32 + mi * 16 + g;
#pragma unroll
        for (int nj = 0; nj < 8; nj++) {
            int col = n0 + wn * 64 + nj * 8 + 2 * tg;
            if (col < N) {
                *(float2*)(g_zx + (size_t)rbase * N + col) =
                    make_float2(acc[mi][nj][0], acc[mi][nj][1]);
                *(float2*)(g_zx + (size_t)(rbase + 8) * N + col) =
                    make_float2(acc[mi][nj][2], acc[mi][nj][3]);
            }
        }
    }
}

// ---------------- kernel 3: dt / dA ----------------
__global__ void dtda_kernel(const float* __restrict__ dt_bias,
                            const float* __restrict__ A_log)
{
    int id = blockIdx.x * blockDim.x + threadIdx.x;
    if (id >= ROWS * NH) return;
    int r = id >> 3, h = id & 7;
    float v = g_zx[(size_t)r * DIN + (DIN - NH) + h] + dt_bias[h];
    float d = (v > 20.f) ? v : log1pf(__expf(v));
    float A = -__expf(A_log[h]);
    g_dt[id] = d;
    g_da[id] = __expf(d * A);
}

// ---------------- kernel 4: conv(4)+SiLU, B/C channels only ----------
#define TROW 8
#define NBC  32
__global__ void convbc_kernel(const float* __restrict__ cw,
                              const float* __restrict__ cb)
{
    int id = blockIdx.x * blockDim.x + threadIdx.x;
    if (id >= (ROWS / TROW) * NBC) return;
    int c  = DINNER + (id % NBC);     // 512..543
    int rb = id / NBC;
    int r0 = rb * TROW;
    int l0 = r0 & (LSEQ - 1);

    const float* col = g_zx + DINNER + c;
    float w0 = cw[c * 4 + 0], w1 = cw[c * 4 + 1];
    float w2 = cw[c * 4 + 2], w3 = cw[c * 4 + 3];
    float bias = cb[c];

    float vm3 = 0.f, vm2 = 0.f, vm1 = 0.f;
    if (l0 != 0) {
        vm3 = col[(size_t)(r0 - 3) * DIN];
        vm2 = col[(size_t)(r0 - 2) * DIN];
        vm1 = col[(size_t)(r0 - 1) * DIN];
    }
#pragma unroll
    for (int i = 0; i < TROW; i++) {
        float v = col[(size_t)(r0 + i) * DIN];
        float acc = bias + w3 * v + w2 * vm1 + w1 * vm2 + w0 * vm3;
        g_xbc[(size_t)(r0 + i) * CONVD + c] = acc * fsig(acc);
        vm3 = vm2; vm2 = vm1; vm1 = v;
    }
}

// ---------------- kernel 5a: segment-local scan, fused x-conv, pipelined ---
__global__ __launch_bounds__(64) void scanA_kernel(
    const float* __restrict__ Dp, const float* __restrict__ cw,
    const float* __restrict__ cb)
{
    const int blk = blockIdx.x;
    const int bh  = blk / SEG;
    const int seg = blk % SEG;
    const int b = bh >> 3, h = bh & 7;
    const int p = threadIdx.x;
    const float Dh = Dp[h];

    const int c = h * HD + p;
    const float w0 = cw[c * 4 + 0], w1 = cw[c * 4 + 1];
    const float w2 = cw[c * 4 + 2], w3 = cw[c * 4 + 3];
    const float cbias = cb[c];
    const float* colz = g_zx + DINNER + c;

    float hs[DS];
#pragma unroll
    for (int n = 0; n < DS; n++) hs[n] = 0.f;
    float prod = 1.f;

    const size_t r0 = (size_t)b * LSEQ + seg * SLEN;
    float vm3 = 0.f, vm2 = 0.f, vm1 = 0.f;
    if (seg != 0) {
        vm3 = colz[(r0 - 3) * DIN];
        vm2 = colz[(r0 - 2) * DIN];
        vm1 = colz[(r0 - 1) * DIN];
    }

    // preload step 0
    float dav = g_da[r0 * NH + h];
    float dtv = g_dt[r0 * NH + h];
    float vz  = colz[r0 * DIN];
    const float* bp = g_xbc + r0 * CONVD + DINNER;
    float4 B0 = *(const float4*)(bp +  0), B1 = *(const float4*)(bp +  4);
    float4 B2 = *(const float4*)(bp +  8), B3 = *(const float4*)(bp + 12);
    float4 C0 = *(const float4*)(bp + 16), C1 = *(const float4*)(bp + 20);
    float4 C2 = *(const float4*)(bp + 24), C3 = *(const float4*)(bp + 28);

    for (int l = 0; l < SLEN; l++) {
        const size_t r = r0 + l;
        // prefetch step l+1
        float dav_n = dav, dtv_n = dtv, vz_n = vz;
        float4 nB0 = B0, nB1 = B1, nB2 = B2, nB3 = B3;
        float4 nC0 = C0, nC1 = C1, nC2 = C2, nC3 = C3;
        if (l + 1 < SLEN) {
            const size_t rn = r + 1;
            dav_n = g_da[rn * NH + h];
            dtv_n = g_dt[rn * NH + h];
            vz_n  = colz[rn * DIN];
            const float* bpn = g_xbc + rn * CONVD + DINNER;
            nB0 = *(const float4*)(bpn +  0); nB1 = *(const float4*)(bpn +  4);
            nB2 = *(const float4*)(bpn +  8); nB3 = *(const float4*)(bpn + 12);
            nC0 = *(const float4*)(bpn + 16); nC1 = *(const float4*)(bpn + 20);
            nC2 = *(const float4*)(bpn + 24); nC3 = *(const float4*)(bpn + 28);
        }

        prod *= dav;
        float ca = cbias + w3 * vz + w2 * vm1 + w1 * vm2 + w0 * vm3;
        float xv = ca * fsig(ca);
        vm3 = vm2; vm2 = vm1; vm1 = vz;

        float bb[DS] = {B0.x,B0.y,B0.z,B0.w, B1.x,B1.y,B1.z,B1.w,
                        B2.x,B2.y,B2.z,B2.w, B3.x,B3.y,B3.z,B3.w};
        float cc[DS] = {C0.x,C0.y,C0.z,C0.w, C1.x,C1.y,C1.z,C1.w,
                        C2.x,C2.y,C2.z,C2.w, C3.x,C3.y,C3.z,C3.w};

        float t1 = dtv * xv;
        float yv0 = 0.f, yv1 = 0.f;
#pragma unroll
        for (int n = 0; n < DS; n += 2) {
            hs[n]   = fmaf(dav, hs[n],   t1 * bb[n]);
            hs[n+1] = fmaf(dav, hs[n+1], t1 * bb[n+1]);
            yv0 = fmaf(hs[n],   cc[n],   yv0);
            yv1 = fmaf(hs[n+1], cc[n+1], yv1);
        }
        g_y[r * DINNER + h * HD + p] = yv0 + yv1 + Dh * xv;

        dav = dav_n; dtv = dtv_n; vz = vz_n;
        B0 = nB0; B1 = nB1; B2 = nB2; B3 = nB3;
        C0 = nC0; C1 = nC1; C2 = nC2; C3 = nC3;
    }

    float* he = g_hend + ((size_t)bh * SEG + seg) * STATE + p * DS;
#pragma unroll
    for (int n = 0; n < DS; n += 4)
        *(float4*)(he + n) = make_float4(hs[n], hs[n+1], hs[n+2], hs[n+3]);
    if (p == 0) g_P[(size_t)bh * SEG + seg] = prod;
}

// ---------------- kernel 5b: compose segment states ----------------
__global__ __launch_bounds__(1024) void scanB_kernel()
{
    const int bh = blockIdx.x;
    const int pn = threadIdx.x;
    __shared__ float sP[SEG];
    if (pn < SEG) sP[pn] = g_P[(size_t)bh * SEG + pn];
    __syncthreads();

    float h = 0.f;
    const size_t base = (size_t)bh * SEG * STATE + pn;
    for (int seg = 0; seg < SEG; seg++) {
        g_hin[base + (size_t)seg * STATE] = h;
        h = fmaf(sP[seg], h, g_hend[base + (size_t)seg * STATE]);
    }
}

// ---------------- kernel 5c: cross-segment correction, pipelined ---------
__global__ __launch_bounds__(64) void scanC_kernel()
{
    const int blk = blockIdx.x;
    const int bh  = blk / (SEG - 1);
    const int seg = blk % (SEG - 1) + 1;
    const int b = bh >> 3, h = bh & 7;
    const int p = threadIdx.x;

    float hi[DS];
    const float* hp = g_hin + ((size_t)bh * SEG + seg) * STATE + p * DS;
#pragma unroll
    for (int n = 0; n < DS; n += 4) {
        float4 v = *(const float4*)(hp + n);
        hi[n] = v.x; hi[n+1] = v.y; hi[n+2] = v.z; hi[n+3] = v.w;
    }

    float cp = 1.f;
    const size_t r0 = (size_t)b * LSEQ + seg * SLEN;

    float dav = g_da[r0 * NH + h];
    const float* bp0 = g_xbc + r0 * CONVD + DINNER;
    float4 C0 = *(const float4*)(bp0 + 16), C1 = *(const float4*)(bp0 + 20);
    float4 C2 = *(const float4*)(bp0 + 24), C3 = *(const float4*)(bp0 + 28);

    for (int l = 0; l < SLEN; l++) {
        const size_t r = r0 + l;
        float dav_n = dav;
        float4 nC0 = C0, nC1 = C1, nC2 = C2, nC3 = C3;
        if (l + 1 < SLEN) {
            const size_t rn = r + 1;
            dav_n = g_da[rn * NH + h];
            const float* bpn = g_xbc + rn * CONVD + DINNER;
            nC0 = *(const float4*)(bpn + 16); nC1 = *(const float4*)(bpn + 20);
            nC2 = *(const float4*)(bpn + 24); nC3 = *(const float4*)(bpn + 28);
        }

        cp *= dav;
        float cc[DS] = {C0.x,C0.y,C0.z,C0.w, C1.x,C1.y,C1.z,C1.w,
                        C2.x,C2.y,C2.z,C2.w, C3.x,C3.y,C3.z,C3.w};
        float d0 = 0.f, d1 = 0.f;
#pragma unroll
        for (int n = 0; n < DS; n += 2) {
            d0 = fmaf(hi[n],   cc[n],   d0);
            d1 = fmaf(hi[n+1], cc[n+1], d1);
        }
        g_y[r * DINNER + h * HD + p] += cp * (d0 + d1);

        dav = dav_n;
        C0 = nC0; C1 = nC1; C2 = nC2; C3 = nC3;
    }
}

// ---------------- GEMM2 fused, pipelined: gate + RMSNorm + out_proj +
// transpose + residual. B copied async from g_wouts; A gate reg-prefetched.
#define G2_ASTRIDE 36
#define G2_BSTRIDE 264
#define G2_BSZ (32*G2_BSTRIDE)                 // 8448 floats per buffer
#define G2_POOLF (64*G2_ASTRIDE + 2*G2_BSZ)    // 2304 + 16896 = 19200 floats
#define SMEM_G2 (G2_POOLF*4)                   // 76800 bytes

__global__ __launch_bounds__(256) void gemm2_fused_kernel(
    const float* __restrict__ x, float* __restrict__ out)
{
    extern __shared__ float pool[];
    float* As = pool;                   // [64][36]
    float* Bs = pool + 64 * G2_ASTRIDE; // [2][32][264]
    const int t = threadIdx.x;
    const int warp = t >> 5, lane = t & 31;
    const int wm = warp & 1, wn = warp >> 1;
    const int m0 = blockIdx.x * 64;
    const int g = lane >> 2, tg = lane & 3;
    const int r0 = t >> 3, kc0 = (t & 7) << 2;

    float acc[2][8][4];
#pragma unroll
    for (int mi = 0; mi < 2; mi++)
#pragma unroll
        for (int nj = 0; nj < 8; nj++)
#pragma unroll
            for (int q = 0; q < 4; q++) acc[mi][nj][q] = 0.f;
    float sq0 = 0.f, sq1 = 0.f;

    auto issueB = [&](int k0, int buf) {
        float* Bsb = Bs + buf * G2_BSZ;
        const float* Wg = g_wouts + (size_t)k0 * CCH;
#pragma unroll
        for (int i = 0; i < 8; i++) {
            int idx = t + i * 256;
            int kr = idx >> 6, nc = (idx & 63) << 2;
            cp16(Bsb + kr * G2_BSTRIDE + nc, Wg + (size_t)kr * CCH + nc);
        }
    };

    // prologue: B tile 0 async; A tile 0 raw loads
    issueB(0, 0);
    CP_COMMIT();
    float4 ry0, ry1, rz0, rz1;
    {
        size_t rra = (size_t)(m0 + r0);
        size_t rrb = (size_t)(m0 + r0 + 32);
        ry0 = *(const float4*)(g_y  + rra * DINNER + kc0);
        rz0 = *(const float4*)(g_zx + rra * DIN    + kc0);
        ry1 = *(const float4*)(g_y  + rrb * DINNER + kc0);
        rz1 = *(const float4*)(g_zx + rrb * DIN    + kc0);
    }

    const int NT = DINNER / 32;   // 16
    for (int kt = 0; kt < NT; kt++) {
        // gate from regs -> As
        {
            float v0 = ry0.x * (rz0.x * fsig(rz0.x));
            float v1 = ry0.y * (rz0.y * fsig(rz0.y));
            float v2 = ry0.z * (rz0.z * fsig(rz0.z));
            float v3 = ry0.w * (rz0.w * fsig(rz0.w));
            As[r0 * G2_ASTRIDE + kc0 + 0] = __uint_as_float(f2tf32(v0));
            As[r0 * G2_ASTRIDE + kc0 + 1] = __uint_as_float(f2tf32(v1));
            As[r0 * G2_ASTRIDE + kc0 + 2] = __uint_as_float(f2tf32(v2));
            As[r0 * G2_ASTRIDE + kc0 + 3] = __uint_as_float(f2tf32(v3));
            sq0 += v0*v0 + v1*v1 + v2*v2 + v3*v3;
            float u0 = ry1.x * (rz1.x * fsig(rz1.x));
            float u1 = ry1.y * (rz1.y * fsig(rz1.y));
            float u2 = ry1.z * (rz1.z * fsig(rz1.z));
            float u3 = ry1.w * (rz1.w * fsig(rz1.w));
            As[(r0 + 32) * G2_ASTRIDE + kc0 + 0] = __uint_as_float(f2tf32(u0));
            As[(r0 + 32) * G2_ASTRIDE + kc0 + 1] = __uint_as_float(f2tf32(u1));
            As[(r0 + 32) * G2_ASTRIDE + kc0 + 2] = __uint_as_float(f2tf32(u2));
            As[(r0 + 32) * G2_ASTRIDE + kc0 + 3] = __uint_as_float(f2tf32(u3));
            sq1 += u0*u0 + u1*u1 + u2*u2 + u3*u3;
        }
        // prefetch next tile (B async, A regs)
        if (kt + 1 < NT) {
            issueB((kt + 1) * 32, (kt + 1) & 1);
            CP_COMMIT();
            int k1 = (kt + 1) * 32 + kc0;
            size_t rra = (size_t)(m0 + r0);
            size_t rrb = (size_t)(m0 + r0 + 32);
            ry0 = *(const float4*)(g_y  + rra * DINNER + k1);
            rz0 = *(const float4*)(g_zx + rra * DIN    + k1);
            ry1 = *(const float4*)(g_y  + rrb * DINNER + k1);
            rz1 = *(const float4*)(g_zx + rrb * DIN    + k1);
            CP_WAIT1();
        } else {
            asm volatile("cp.async.wait_group 0;");
        }
        __syncthreads();

        const float* Bsb = Bs + (kt & 1) * G2_BSZ;
#pragma unroll
        for (int kk = 0; kk < 32; kk += 8) {
            uint32_t af[2][4];
#pragma unroll
            for (int mi = 0; mi < 2; mi++) {
                int mb = wm * 32 + mi * 16;
                af[mi][0] = __float_as_uint(As[(mb + g    ) * G2_ASTRIDE + kk + tg]);
                af[mi][1] = __float_as_uint(As[(mb + 8 + g) * G2_ASTRIDE + kk + tg]);
                af[mi][2] = __float_as_uint(As[(mb + g    ) * G2_ASTRIDE + kk + 4 + tg]);
                af[mi][3] = __float_as_uint(As[(mb + 8 + g) * G2_ASTRIDE + kk + 4 + tg]);
            }
            uint32_t bf[8][2];
#pragma unroll
            for (int nj = 0; nj < 8; nj++) {
                int nb = wn * 64 + nj * 8;
                bf[nj][0] = __float_as_uint(Bsb[(kk + tg    ) * G2_BSTRIDE + nb + g]);
                bf[nj][1] = __float_as_uint(Bsb[(kk + 4 + tg) * G2_BSTRIDE + nb + g]);
            }
#pragma unroll
            for (int mi = 0; mi < 2; mi++)
#pragma unroll
                for (int nj = 0; nj < 8; nj++) MMA_TF32(acc[mi][nj], af[mi], bf[nj]);
        }
        __syncthreads();
    }

    // rn reduction (As region reused)
    float* sq = pool;
    sq[r0 * 8 + (t & 7)] = sq0;
    sq[(r0 + 32) * 8 + (t & 7)] = sq1;
    __syncthreads();
    float* rn = pool + 512;
    if (t < 64) {
        float s = 0.f;
#pragma unroll
        for (int j = 0; j < 8; j++) s += sq[t * 8 + j];
        rn[t] = rsqrtf(s * (1.f / (float)DINNER) + EPS);
    }
    __syncthreads();
    float rsc[2][2];
#pragma unroll
    for (int mi = 0; mi < 2; mi++) {
        rsc[mi][0] = rn[wm * 32 + mi * 16 + g];
        rsc[mi][1] = rn[wm * 32 + mi * 16 + 8 + g];
    }
    __syncthreads();

    // epilogue: transpose + residual
    float* epi = pool;
    const int b  = m0 >> 12;
    const int l0 = m0 & (LSEQ - 1);
#pragma unroll
    for (int cj = 0; cj < 4; cj++) {
        if (wn == cj) {
#pragma unroll
            for (int mi = 0; mi < 2; mi++)
#pragma unroll
                for (int nj = 0; nj < 8; nj++)
#pragma unroll
                    for (int q = 0; q < 4; q++) {
                        int Rl = wm * 32 + mi * 16 + g + ((q >> 1) << 3);
                        int cl = nj * 8 + 2 * tg + (q & 1);
                        epi[cl * 68 + Rl] = acc[mi][nj][q] * rsc[mi][q >> 1];
                    }
        }
        __syncthreads();
        {
            int c = t >> 2, seg = t & 3;
            size_t ob = ((size_t)b * CCH + cj * 64 + c) * LSEQ + l0 + seg * 16;
#pragma unroll
            for (int j = 0; j < 4; j++) {
                float4 e  = *(float4*)(epi + c * 68 + seg * 16 + j * 4);
                float4 xr = *(const float4*)(x + ob + j * 4);
                e.x += xr.x; e.y += xr.y; e.z += xr.z; e.w += xr.w;
                *(float4*)(out + ob + j * 4) = e;
            }
        }
        __syncthreads();
    }
}

extern "C" void kernel_launch(void* const* d_in, const int* in_sizes, int n_in,
                              void* d_out, int out_size)
{
    const float* x       = (const float*)d_in[0];
    const float* ln_g    = (const float*)d_in[1];
    const float* ln_b    = (const float*)d_in[2];
    const float* Win     = (const float*)d_in[3];
    const float* Wout    = (const float*)d_in[4];
    const float* conv_w  = (const float*)d_in[5];
    const float* conv_b  = (const float*)d_in[6];
    const float* dt_bias = (const float*)d_in[7];
    const float* A_log   = (const float*)d_in[8];
    const float* Dp      = (const float*)d_in[9];
    const float* rms_w   = (const float*)d_in[10];
    float* out = (float*)d_out;

    cudaFuncSetAttribute(gemm1_kernel,
                         cudaFuncAttributeMaxDynamicSharedMemorySize, SMEM_G1);
    cudaFuncSetAttribute(gemm2_fused_kernel,
                         cudaFuncAttributeMaxDynamicSharedMemorySize, SMEM_G2);

    // 0) precompute TF32 weights (Win, Wout*rms_w)
    prep_kernel<<<(CCH * DIN + 255) / 256, 256>>>(Win, Wout, rms_w);

    // 1) layernorm (writes pre-rounded un)
    ln_kernel<<<dim3(LSEQ / 32, BATCH), 256>>>(x, ln_g, ln_b);

    // 2) in_proj GEMM
    gemm1_kernel<<<dim3((DIN + 127) / 128, ROWS / 128), 256, SMEM_G1>>>();

    // 3) dt / dA
    dtda_kernel<<<(ROWS * NH + 255) / 256, 256>>>(dt_bias, A_log);

    // 4) conv + silu, B/C channels only
    convbc_kernel<<<((ROWS / TROW) * NBC + 255) / 256, 256>>>(conv_w, conv_b);

    // 5) segmented SSM scan
    scanA_kernel<<<NBH * SEG, HD>>>(Dp, conv_w, conv_b);
    scanB_kernel<<<NBH, STATE>>>();
    scanC_kernel<<<NBH * (SEG - 1), HD>>>();

    // 6+7+8) fused pipelined: gate + rmsnorm + out_proj + transpose + residual
    gemm2_fused_kernel<<<ROWS / 64, 256, SMEM_G2>>>(x, out);
}